// round 3
// baseline (speedup 1.0000x reference)
#include <cuda_runtime.h>
#include <cuda_bf16.h>
#include <math.h>

#define B      128
#define D      524288          // 512*32*32
#define D4     (D/4)           // 131072 float4 per row
#define NC     12
#define KT4    32              // float4 per row per k1 chunk (128 floats)
#define NCHUNK (D4/KT4)        // 4096
#define NCTA   148
#define K1_THREADS 512
#define NP     64              // row pairs (128 rows / 2)

// -------- device scratch (no allocation allowed) --------
__device__ float g_pd[B * B];     // pair dots [s][b], s<=b, slot-indexed
__device__ float g_wslot[B];      // normalized weights (slot order)
__device__ int   g_members[B];    // slot -> sample index (class-sorted)
__device__ int   g_start[NC + 1]; // class segment starts (slots)
__device__ int   g_send[B];       // slot -> class end slot
__device__ int   g_wp[NP * 2];    // pair p -> two row slots
__device__ int   g_wpk[NP];       // pair p -> max partner count of its rows

// =====================================================================
// k0: zero pd; class-sort slots; balance rows into 64 half-warp pairs
// =====================================================================
__global__ void k0_prep(const int* __restrict__ labels) {
    __shared__ int sl[B];
    int t = threadIdx.x;
    sl[t] = labels[t];
    for (int p = t; p < B * B; p += B) g_pd[p] = 0.0f;
    __syncthreads();
    if (t == 0) {
        int cnt[NC];
        for (int c = 0; c < NC; ++c) cnt[c] = 0;
        for (int i = 0; i < B; ++i) cnt[sl[i]]++;
        int st = 0;
        for (int c = 0; c < NC; ++c) { g_start[c] = st; st += cnt[c]; cnt[c] = g_start[c]; }
        g_start[NC] = st;
        for (int i = 0; i < B; ++i) g_members[cnt[sl[i]]++] = i;
        for (int c = 0; c < NC; ++c)
            for (int s = g_start[c]; s < g_start[c + 1]; ++s)
                g_send[s] = g_start[c + 1];
        // sort rows desc by partner count (e - s), pair rank-adjacent
        int idx[B], key[B];
        for (int r = 0; r < B; ++r) { idx[r] = r; key[r] = g_send[r] - r; }
        for (int i = 1; i < B; ++i) {           // insertion sort desc
            int ki = key[i], vi = idx[i], j = i - 1;
            while (j >= 0 && key[j] < ki) { key[j+1] = key[j]; idx[j+1] = idx[j]; --j; }
            key[j+1] = ki; idx[j+1] = vi;
        }
        for (int p = 0; p < NP; ++p) {
            int r0 = idx[2*p], r1 = idx[2*p + 1];
            g_wp[p*2 + 0] = r0;
            g_wp[p*2 + 1] = r1;
            int c0 = g_send[r0] - r0, c1 = g_send[r1] - r1;
            g_wpk[p] = (c0 > c1) ? c0 : c1;
        }
    }
}

// =====================================================================
// cp.async helpers
// =====================================================================
__device__ __forceinline__ void cp16(float4* smem_dst, const float4* gmem_src) {
    unsigned s = (unsigned)__cvta_generic_to_shared(smem_dst);
    asm volatile("cp.async.cg.shared.global [%0], [%1], 16;\n" :: "r"(s), "l"(gmem_src));
}
#define CP_COMMIT() asm volatile("cp.async.commit_group;\n" ::: "memory")
#define CP_WAIT1()  asm volatile("cp.async.wait_group 1;\n"  ::: "memory")

// =====================================================================
// k1: persistent masked pair dots, double-buffered tiles, half-warp rows
// =====================================================================
__global__ void __launch_bounds__(K1_THREADS, 1)
k1_pairdots(const float* __restrict__ features) {
    extern __shared__ float4 S[];          // [2][B*KT4]  (2 x 64 KB)
    __shared__ int s_m[B];                 // slot -> gmem row
    __shared__ int s_e[B];                 // slot -> class end
    __shared__ int s_wp[NP * 2];
    __shared__ int s_wpk[NP];

    const int tid  = threadIdx.x;
    const int wid  = tid >> 5;
    const int lane = tid & 31;
    const int hl   = lane & 15;            // lane within half-warp
    const int half = lane >> 4;            // which half

    if (tid < B)      { s_m[tid] = g_members[tid]; s_e[tid] = g_send[tid]; }
    if (tid < NP * 2) s_wp[tid]  = g_wp[tid];
    if (tid < NP)     s_wpk[tid] = g_wpk[tid];
    __syncthreads();

    const float4* F4 = (const float4*)features;

    // tile loader: 128 rows x 32 float4, coalesced 512B per warp-instr
    auto load_tile = [&](float4* dst, int chunk) {
        const int base4 = chunk * KT4;
        #pragma unroll
        for (int k = 0; k < (B * KT4) / K1_THREADS; ++k) {   // 8
            int idx = tid + k * K1_THREADS;
            int r = idx >> 5, c = idx & 31;
            cp16(&dst[idx], &F4[(size_t)s_m[r] * D4 + base4 + c]);
        }
    };

    const int c0 = blockIdx.x;
    if (c0 < NCHUNK) load_tile(S, c0);
    CP_COMMIT();

    int it = 0;
    for (int c = c0; c < NCHUNK; c += NCTA, ++it) {
        int nxt = c + NCTA;
        if (nxt < NCHUNK) load_tile(S + ((it + 1) & 1) * (B * KT4), nxt);
        CP_COMMIT();
        CP_WAIT1();                        // current chunk's tile complete
        __syncthreads();

        const float4* T = S + (it & 1) * (B * KT4);

        #pragma unroll
        for (int q = 0; q < 4; ++q) {
            const int ps  = wid + q * 16;          // pair slot for this warp
            const int r   = s_wp[ps * 2 + half];   // this half's row
            const int cnt = s_e[r] - r;            // partners incl. diagonal
            const int kmax = s_wpk[ps];
            const float4 a0 = T[r * KT4 + hl];
            const float4 a1 = T[r * KT4 + 16 + hl];
            #pragma unroll 2
            for (int k = 0; k < kmax; ++k) {
                const bool act = (k < cnt);
                const int b = act ? (r + k) : r;
                float4 b0 = T[b * KT4 + hl];
                float4 b1 = T[b * KT4 + 16 + hl];
                float p = a0.x * b0.x + a0.y * b0.y + a0.z * b0.z + a0.w * b0.w
                        + a1.x * b1.x + a1.y * b1.y + a1.z * b1.z + a1.w * b1.w;
                p += __shfl_down_sync(0xFFFFFFFFu, p, 8, 16);
                p += __shfl_down_sync(0xFFFFFFFFu, p, 4, 16);
                p += __shfl_down_sync(0xFFFFFFFFu, p, 2, 16);
                p += __shfl_down_sync(0xFFFFFFFFu, p, 1, 16);
                if (act && hl == 0) atomicAdd(&g_pd[r * B + b], p);
            }
        }
        __syncthreads();                   // buffer reuse fence
    }
}

// =====================================================================
// k2: distances -> dsum -> smoothed normalized weights (slot order)
// =====================================================================
__global__ void k2_weights() {
    __shared__ float sdiag[B];
    __shared__ float swv[B];
    __shared__ float ssum;
    __shared__ int sst[NC + 1];
    int s = threadIdx.x;
    if (s < NC + 1) sst[s] = g_start[s];
    sdiag[s] = g_pd[s * B + s];
    __syncthreads();

    int st = 0, en = 0;
    for (int c = 0; c < NC; ++c)
        if (s >= sst[c] && s < sst[c + 1]) { st = sst[c]; en = sst[c + 1]; }

    float dsum = 0.0f;
    for (int b = st; b < en; ++b) {
        if (b == s) continue;
        float pd = (b >= s) ? g_pd[s * B + b] : g_pd[b * B + s];
        float d2 = sdiag[s] + sdiag[b] - 2.0f * pd;
        dsum += (d2 > 0.0f) ? sqrtf(d2) : 0.0f;
    }
    float w = 1.0f / (sqrtf(dsum * dsum + 25.0f) + 1e-12f);
    swv[s] = w;
    __syncthreads();
    if (s == 0) {
        float S = 0.0f;
        for (int t = 0; t < B; ++t) S += swv[t];
        ssum = S;
    }
    __syncthreads();
    g_wslot[s] = w / (ssum + 1e-12f);
}

// =====================================================================
// k3: weighted class scatter-sum, rolling slot pass, 8-deep prefetch
// =====================================================================
#define PF 8
__global__ void __launch_bounds__(256) k3_scatter(const float* __restrict__ features,
                                                  float* __restrict__ out) {
    __shared__ float sw[B];
    __shared__ int   sm[B];
    __shared__ int   sst[NC + 1];
    int t = threadIdx.x;
    if (t < B)      { sw[t] = g_wslot[t]; sm[t] = g_members[t]; }
    if (t < NC + 1) { sst[t] = g_start[t]; }
    __syncthreads();

    const size_t t4 = (size_t)blockIdx.x * 256 + t;
    const float4* F4 = (const float4*)features;
    float4* O4 = (float4*)out;

    float4 buf[PF];
    #pragma unroll
    for (int k = 0; k < PF; ++k)
        buf[k] = F4[(size_t)sm[k] * D4 + t4];

    int c = 0;
    int nb = sst[1];
    float4 acc = make_float4(0.f, 0.f, 0.f, 0.f);

    for (int s0 = 0; s0 < B; s0 += PF) {
        #pragma unroll
        for (int k = 0; k < PF; ++k) {
            int s = s0 + k;
            while (s == nb && c < NC) {
                O4[(size_t)c * D4 + t4] = acc;
                acc = make_float4(0.f, 0.f, 0.f, 0.f);
                ++c;
                nb = sst[c + 1];
            }
            float4 v = buf[k];
            float w = sw[s];
            acc.x += w * v.x; acc.y += w * v.y;
            acc.z += w * v.z; acc.w += w * v.w;
            int sp = s + PF;
            if (sp < B) buf[k] = F4[(size_t)sm[sp] * D4 + t4];
        }
    }
    while (c < NC) {
        O4[(size_t)c * D4 + t4] = acc;
        acc = make_float4(0.f, 0.f, 0.f, 0.f);
        ++c;
    }
}

// =====================================================================
extern "C" void kernel_launch(void* const* d_in, const int* in_sizes, int n_in,
                              void* d_out, int out_size) {
    const float* features;
    const int*   labels;
    if (in_sizes[0] == B) {
        labels   = (const int*)d_in[0];
        features = (const float*)d_in[1];
    } else {
        features = (const float*)d_in[0];
        labels   = (const int*)d_in[1];
    }
    float* out = (float*)d_out;

    const int k1_smem = 2 * B * KT4 * (int)sizeof(float4);   // 128 KB
    (void)cudaFuncSetAttribute((const void*)k1_pairdots,
                               cudaFuncAttributeMaxDynamicSharedMemorySize,
                               k1_smem);

    k0_prep<<<1, B>>>(labels);
    k1_pairdots<<<NCTA, K1_THREADS, k1_smem>>>(features);
    k2_weights<<<1, B>>>();
    k3_scatter<<<D4 / 256, 256>>>(features, out);
}

// round 4
// speedup vs baseline: 1.9918x; 1.9918x over previous
#include <cuda_runtime.h>
#include <cuda_bf16.h>
#include <math.h>

#define B      128
#define D      524288          // 512*32*32
#define D4     (D/4)           // 131072 float4 per row
#define NC     12
#define KT4    32              // float4 per row per k1 chunk (128 floats)
#define NCHUNK (D4/KT4)        // 4096
#define NCTA   148
#define K1_THREADS 512
#define NP     64              // row pairs (128 rows / 2)

// -------- device scratch (no allocation allowed) --------
__device__ float g_pd[B * B];     // pair dots [s][b], s<=b, slot-indexed
__device__ float g_wslot[B];      // normalized weights (slot order)
__device__ int   g_members[B];    // slot -> sample index (class-sorted)
__device__ int   g_start[NC + 1]; // class segment starts (slots)
__device__ int   g_send[B];       // slot -> class end slot
__device__ int   g_wp[NP * 2];    // pair p -> two row slots
__device__ int   g_wpk[NP];       // pair p -> max partner count of its rows

// =====================================================================
// k0: zero pd; class-sort slots; balance rows into 64 half-warp pairs.
// FULLY PARALLEL (no single-thread sorts, no local-memory arrays).
// =====================================================================
__global__ void k0_prep(const int* __restrict__ labels) {
    __shared__ int sl[B];        // labels
    __shared__ int cstart[NC + 1];
    __shared__ int send_s[B];    // slot -> class end
    __shared__ int skey[B];      // slot -> partner count
    __shared__ int sorder[B];    // rank -> slot (desc by key, stable)
    int t = threadIdx.x;
    sl[t] = labels[t];
    for (int p = t; p < B * B; p += B) g_pd[p] = 0.0f;
    __syncthreads();

    // class counts -> starts (tiny serial scan over 12 classes)
    if (t == 0) {
        int cnt[NC];
        for (int c = 0; c < NC; ++c) cnt[c] = 0;
        for (int i = 0; i < B; ++i) cnt[sl[i]]++;
        int st = 0;
        for (int c = 0; c < NC; ++c) { cstart[c] = st; st += cnt[c]; }
        cstart[NC] = st;
    }
    __syncthreads();

    // slot of sample t = class start + rank among same-label earlier samples
    {
        int my = sl[t];
        int r = 0;
        for (int j = 0; j < t; ++j) r += (sl[j] == my);
        int slot = cstart[my] + r;
        g_members[slot] = t;
        send_s[slot] = cstart[my + 1];
    }
    if (t < NC + 1) g_start[t] = cstart[t];
    __syncthreads();

    g_send[t] = send_s[t];
    skey[t] = send_s[t] - t;               // partner count (incl. self)
    __syncthreads();

    // stable descending rank of slot t by key (parallel O(B) per thread)
    {
        int k = skey[t];
        int rank = 0;
        for (int s = 0; s < B; ++s) {
            int ks = skey[s];
            rank += (ks > k) || (ks == k && s < t);
        }
        sorder[rank] = t;
    }
    __syncthreads();

    // pair rank-adjacent slots into NP half-warp tasks
    if (t < NP) {
        int r0 = sorder[2 * t], r1 = sorder[2 * t + 1];
        g_wp[t * 2 + 0] = r0;
        g_wp[t * 2 + 1] = r1;
        int c0 = skey[r0], c1 = skey[r1];
        g_wpk[t] = (c0 > c1) ? c0 : c1;
    }
}

// =====================================================================
// cp.async helpers
// =====================================================================
__device__ __forceinline__ void cp16(float4* smem_dst, const float4* gmem_src) {
    unsigned s = (unsigned)__cvta_generic_to_shared(smem_dst);
    asm volatile("cp.async.cg.shared.global [%0], [%1], 16;\n" :: "r"(s), "l"(gmem_src));
}
#define CP_COMMIT() asm volatile("cp.async.commit_group;\n" ::: "memory")
#define CP_WAIT1()  asm volatile("cp.async.wait_group 1;\n"  ::: "memory")

// =====================================================================
// k1: persistent masked pair dots, double-buffered tiles, half-warp rows
// =====================================================================
__global__ void __launch_bounds__(K1_THREADS, 1)
k1_pairdots(const float* __restrict__ features) {
    extern __shared__ float4 S[];          // [2][B*KT4]  (2 x 64 KB)
    __shared__ int s_m[B];                 // slot -> gmem row
    __shared__ int s_e[B];                 // slot -> class end
    __shared__ int s_wp[NP * 2];
    __shared__ int s_wpk[NP];

    const int tid  = threadIdx.x;
    const int wid  = tid >> 5;
    const int lane = tid & 31;
    const int hl   = lane & 15;            // lane within half-warp
    const int half = lane >> 4;            // which half

    if (tid < B)      { s_m[tid] = g_members[tid]; s_e[tid] = g_send[tid]; }
    if (tid < NP * 2) s_wp[tid]  = g_wp[tid];
    if (tid < NP)     s_wpk[tid] = g_wpk[tid];
    __syncthreads();

    const float4* F4 = (const float4*)features;

    auto load_tile = [&](float4* dst, int chunk) {
        const int base4 = chunk * KT4;
        #pragma unroll
        for (int k = 0; k < (B * KT4) / K1_THREADS; ++k) {   // 8
            int idx = tid + k * K1_THREADS;
            int r = idx >> 5, c = idx & 31;
            cp16(&dst[idx], &F4[(size_t)s_m[r] * D4 + base4 + c]);
        }
    };

    const int c0 = blockIdx.x;
    if (c0 < NCHUNK) load_tile(S, c0);
    CP_COMMIT();

    int it = 0;
    for (int c = c0; c < NCHUNK; c += NCTA, ++it) {
        int nxt = c + NCTA;
        if (nxt < NCHUNK) load_tile(S + ((it + 1) & 1) * (B * KT4), nxt);
        CP_COMMIT();
        CP_WAIT1();                        // current chunk's tile complete
        __syncthreads();

        const float4* T = S + (it & 1) * (B * KT4);

        #pragma unroll
        for (int q = 0; q < 4; ++q) {
            const int ps  = wid + q * 16;          // pair slot for this warp
            const int r   = s_wp[ps * 2 + half];   // this half's row
            const int cnt = s_e[r] - r;            // partners incl. diagonal
            const int kmax = s_wpk[ps];
            const float4 a0 = T[r * KT4 + hl];
            const float4 a1 = T[r * KT4 + 16 + hl];
            #pragma unroll 2
            for (int k = 0; k < kmax; ++k) {
                const bool act = (k < cnt);
                const int b = act ? (r + k) : r;
                float4 b0 = T[b * KT4 + hl];
                float4 b1 = T[b * KT4 + 16 + hl];
                float p = a0.x * b0.x + a0.y * b0.y + a0.z * b0.z + a0.w * b0.w
                        + a1.x * b1.x + a1.y * b1.y + a1.z * b1.z + a1.w * b1.w;
                p += __shfl_down_sync(0xFFFFFFFFu, p, 8, 16);
                p += __shfl_down_sync(0xFFFFFFFFu, p, 4, 16);
                p += __shfl_down_sync(0xFFFFFFFFu, p, 2, 16);
                p += __shfl_down_sync(0xFFFFFFFFu, p, 1, 16);
                if (act && hl == 0) atomicAdd(&g_pd[r * B + b], p);
            }
        }
        __syncthreads();                   // buffer reuse fence
    }
}

// =====================================================================
// k2: distances -> dsum -> smoothed normalized weights (slot order)
// =====================================================================
__global__ void k2_weights() {
    __shared__ float sdiag[B];
    __shared__ float swv[B];
    __shared__ float ssum;
    __shared__ int sst[NC + 1];
    int s = threadIdx.x;
    if (s < NC + 1) sst[s] = g_start[s];
    sdiag[s] = g_pd[s * B + s];
    __syncthreads();

    int st = 0, en = 0;
    for (int c = 0; c < NC; ++c)
        if (s >= sst[c] && s < sst[c + 1]) { st = sst[c]; en = sst[c + 1]; }

    float dsum = 0.0f;
    for (int b = st; b < en; ++b) {
        if (b == s) continue;
        float pd = (b >= s) ? g_pd[s * B + b] : g_pd[b * B + s];
        float d2 = sdiag[s] + sdiag[b] - 2.0f * pd;
        dsum += (d2 > 0.0f) ? sqrtf(d2) : 0.0f;
    }
    float w = 1.0f / (sqrtf(dsum * dsum + 25.0f) + 1e-12f);
    swv[s] = w;
    __syncthreads();
    if (s == 0) {
        float S = 0.0f;
        for (int t = 0; t < B; ++t) S += swv[t];
        ssum = S;
    }
    __syncthreads();
    g_wslot[s] = w / (ssum + 1e-12f);
}

// =====================================================================
// k3: weighted class scatter-sum, rolling slot pass, 8-deep prefetch
// =====================================================================
#define PF 8
__global__ void __launch_bounds__(256) k3_scatter(const float* __restrict__ features,
                                                  float* __restrict__ out) {
    __shared__ float sw[B];
    __shared__ int   sm[B];
    __shared__ int   sst[NC + 1];
    int t = threadIdx.x;
    if (t < B)      { sw[t] = g_wslot[t]; sm[t] = g_members[t]; }
    if (t < NC + 1) { sst[t] = g_start[t]; }
    __syncthreads();

    const size_t t4 = (size_t)blockIdx.x * 256 + t;
    const float4* F4 = (const float4*)features;
    float4* O4 = (float4*)out;

    float4 buf[PF];
    #pragma unroll
    for (int k = 0; k < PF; ++k)
        buf[k] = F4[(size_t)sm[k] * D4 + t4];

    int c = 0;
    int nb = sst[1];
    float4 acc = make_float4(0.f, 0.f, 0.f, 0.f);

    for (int s0 = 0; s0 < B; s0 += PF) {
        #pragma unroll
        for (int k = 0; k < PF; ++k) {
            int s = s0 + k;
            while (s == nb && c < NC) {
                O4[(size_t)c * D4 + t4] = acc;
                acc = make_float4(0.f, 0.f, 0.f, 0.f);
                ++c;
                nb = sst[c + 1];
            }
            float4 v = buf[k];
            float w = sw[s];
            acc.x += w * v.x; acc.y += w * v.y;
            acc.z += w * v.z; acc.w += w * v.w;
            int sp = s + PF;
            if (sp < B) buf[k] = F4[(size_t)sm[sp] * D4 + t4];
        }
    }
    while (c < NC) {
        O4[(size_t)c * D4 + t4] = acc;
        acc = make_float4(0.f, 0.f, 0.f, 0.f);
        ++c;
    }
}

// =====================================================================
extern "C" void kernel_launch(void* const* d_in, const int* in_sizes, int n_in,
                              void* d_out, int out_size) {
    const float* features;
    const int*   labels;
    if (in_sizes[0] == B) {
        labels   = (const int*)d_in[0];
        features = (const float*)d_in[1];
    } else {
        features = (const float*)d_in[0];
        labels   = (const int*)d_in[1];
    }
    float* out = (float*)d_out;

    const int k1_smem = 2 * B * KT4 * (int)sizeof(float4);   // 128 KB
    (void)cudaFuncSetAttribute((const void*)k1_pairdots,
                               cudaFuncAttributeMaxDynamicSharedMemorySize,
                               k1_smem);

    k0_prep<<<1, B>>>(labels);
    k1_pairdots<<<NCTA, K1_THREADS, k1_smem>>>(features);
    k2_weights<<<1, B>>>();
    k3_scatter<<<D4 / 256, 256>>>(features, out);
}

// round 5
// speedup vs baseline: 2.6734x; 1.3422x over previous
#include <cuda_runtime.h>
#include <cuda_bf16.h>
#include <math.h>

#define B      128
#define D      524288          // 512*32*32
#define D4     (D/4)           // 131072 float4 per row
#define NC     12
#define KT4    32              // float4 per row per k1 chunk (128 floats)
#define NCHUNK (D4/KT4)        // 4096
#define NCTA   148
#define K1_THREADS 512
#define KB     4               // partners per task
#define NJMAX  10              // register-accumulated units per warp
#define NU_FAST (16*NJMAX)     // 160 fast-path warp-units
#define NTASK_SM (2*NU_FAST)   // 320 tasks staged in smem
#define NTASK_MAX 4096         // pathological upper bound

// -------- device scratch (no allocation allowed) --------
__device__ float g_pd[B * B];     // pair dots [s][b], s<=b, slot-indexed
__device__ float g_wslot[B];      // normalized weights (slot order)
__device__ int   g_members[B];    // slot -> sample index (class-sorted)
__device__ int   g_start[NC + 1]; // class segment starts (slots)
__device__ int   g_send[B];       // slot -> class end slot
__device__ int   g_tasks[NTASK_MAX]; // (slot<<8)|partner_offset
__device__ int   g_ntasks;

// =====================================================================
// k0: zero pd; class-sort slots; emit (row, partner-block) task list.
// Fully parallel except tiny SMEM-resident scans.
// =====================================================================
__global__ void k0_prep(const int* __restrict__ labels) {
    __shared__ int sl[B];
    __shared__ int cstart[NC + 1];
    __shared__ int send_s[B];
    __shared__ int toff[B + 1];
    int t = threadIdx.x;
    sl[t] = labels[t];
    for (int p = t; p < B * B; p += B) g_pd[p] = 0.0f;
    __syncthreads();

    if (t == 0) {
        int cnt[NC];
        for (int c = 0; c < NC; ++c) cnt[c] = 0;
        for (int i = 0; i < B; ++i) cnt[sl[i]]++;
        int st = 0;
        for (int c = 0; c < NC; ++c) { cstart[c] = st; st += cnt[c]; }
        cstart[NC] = st;
    }
    __syncthreads();

    // slot of sample t = class start + rank among earlier same-label samples
    {
        int my = sl[t];
        int r = 0;
        for (int j = 0; j < t; ++j) r += (sl[j] == my);
        int slot = cstart[my] + r;
        g_members[slot] = t;
        send_s[slot] = cstart[my + 1];
    }
    if (t < NC + 1) g_start[t] = cstart[t];
    __syncthreads();

    g_send[t] = send_s[t];
    // task-count prefix over slots (tiny serial SMEM scan)
    if (t == 0) {
        int acc = 0;
        for (int s = 0; s < B; ++s) {
            toff[s] = acc;
            int cnt = send_s[s] - s;          // partners incl. diagonal
            acc += (cnt + KB - 1) / KB;
        }
        toff[B] = acc;
        g_ntasks = acc;
    }
    __syncthreads();

    // emit this slot's tasks
    {
        int s = t;
        int cnt = send_s[s] - s;
        int base = toff[s];
        for (int i = 0, off = 0; off < cnt; ++i, off += KB)
            g_tasks[base + i] = (s << 8) | off;
    }
}

// =====================================================================
// cp.async helpers
// =====================================================================
__device__ __forceinline__ void cp16(float4* smem_dst, const float4* gmem_src) {
    unsigned s = (unsigned)__cvta_generic_to_shared(smem_dst);
    asm volatile("cp.async.cg.shared.global [%0], [%1], 16;\n" :: "r"(s), "l"(gmem_src));
}
#define CP_COMMIT() asm volatile("cp.async.commit_group;\n" ::: "memory")
#define CP_WAIT1()  asm volatile("cp.async.wait_group 1;\n"  ::: "memory")

__device__ __forceinline__ float dot8(float4 a0, float4 a1, float4 b0, float4 b1) {
    return a0.x * b0.x + a0.y * b0.y + a0.z * b0.z + a0.w * b0.w
         + a1.x * b1.x + a1.y * b1.y + a1.z * b1.z + a1.w * b1.w;
}

// =====================================================================
// k1: persistent masked pair dots. Double-buffered 64KB tiles. Each
// half-warp owns tasks (row, 4-partner block); per-lane partials are
// accumulated in REGISTERS across all chunks; SHFL reduce + one global
// atomicAdd per pair per CTA happen once at the end.
// =====================================================================
__global__ void __launch_bounds__(K1_THREADS, 1)
k1_pairdots(const float* __restrict__ features) {
    extern __shared__ float4 S[];          // [2][B*KT4] = 2 x 64 KB
    __shared__ int s_m[B];
    __shared__ int s_e[B];
    __shared__ int s_task[NTASK_SM];

    const int tid  = threadIdx.x;
    const int wid  = tid >> 5;
    const int lane = tid & 31;
    const int hl   = lane & 15;
    const int half = lane >> 4;

    if (tid < B) { s_m[tid] = g_members[tid]; s_e[tid] = g_send[tid]; }
    const int T = g_ntasks;
    for (int i = tid; i < NTASK_SM; i += K1_THREADS)
        s_task[i] = (i < T) ? g_tasks[i] : 0;
    __syncthreads();

    const float4* F4 = (const float4*)features;

    auto load_tile = [&](float4* dst, int chunk) {
        const int base4 = chunk * KT4;
        #pragma unroll
        for (int k = 0; k < (B * KT4) / K1_THREADS; ++k) {   // 8
            int idx = tid + k * K1_THREADS;
            int r = idx >> 5, c = idx & 31;
            cp16(&dst[idx], &F4[(size_t)s_m[r] * D4 + base4 + c]);
        }
    };

    float acc[NJMAX][KB];
    #pragma unroll
    for (int j = 0; j < NJMAX; ++j)
        #pragma unroll
        for (int kk = 0; kk < KB; ++kk) acc[j][kk] = 0.0f;

    const bool slow = (T > NTASK_SM);      // pathological fallback active?

    const int c0 = blockIdx.x;
    if (c0 < NCHUNK) load_tile(S, c0);
    CP_COMMIT();

    int it = 0;
    for (int c = c0; c < NCHUNK; c += NCTA, ++it) {
        int nxt = c + NCTA;
        if (nxt < NCHUNK) load_tile(S + ((it + 1) & 1) * (B * KT4), nxt);
        CP_COMMIT();
        CP_WAIT1();
        __syncthreads();

        const float4* Tb = S + (it & 1) * (B * KT4);

        // ---- fast path: register-accumulated units ----
        #pragma unroll
        for (int j = 0; j < NJMAX; ++j) {
            const int u = wid + j * 16;            // warp-uniform unit id
            if (2 * u >= T) continue;              // uniform skip
            const int ti = 2 * u + half;
            const int task = s_task[(ti < T) ? ti : (2 * u)];
            const int r   = task >> 8;
            const int off = task & 255;
            const int cnt = s_e[r] - r;
            const bool lv = (ti < T);
            const float4 a0 = Tb[r * KT4 + hl];
            const float4 a1 = Tb[r * KT4 + 16 + hl];
            #pragma unroll
            for (int kk = 0; kk < KB; ++kk) {
                const int k = off + kk;
                const bool act = lv && (k < cnt);
                const int b = act ? (r + k) : r;
                float4 b0 = Tb[b * KT4 + hl];
                float4 b1 = Tb[b * KT4 + 16 + hl];
                acc[j][kk] += dot8(a0, a1, b0, b1);
            }
        }

        // ---- slow path (only if T > NTASK_SM): per-chunk reduce ----
        if (slow) {
            for (int u = NU_FAST + wid; 2 * u < T; u += 16) {
                const int ti = 2 * u + half;
                const int task = g_tasks[(ti < T) ? ti : (2 * u)];
                const int r   = task >> 8;
                const int off = task & 255;
                const int cnt = s_e[r] - r;
                const bool lv = (ti < T);
                const float4 a0 = Tb[r * KT4 + hl];
                const float4 a1 = Tb[r * KT4 + 16 + hl];
                for (int kk = 0; kk < KB; ++kk) {
                    const int k = off + kk;
                    const bool act = lv && (k < cnt);
                    const int b = act ? (r + k) : r;
                    float4 b0 = Tb[b * KT4 + hl];
                    float4 b1 = Tb[b * KT4 + 16 + hl];
                    float p = dot8(a0, a1, b0, b1);
                    p += __shfl_down_sync(0xFFFFFFFFu, p, 8, 16);
                    p += __shfl_down_sync(0xFFFFFFFFu, p, 4, 16);
                    p += __shfl_down_sync(0xFFFFFFFFu, p, 2, 16);
                    p += __shfl_down_sync(0xFFFFFFFFu, p, 1, 16);
                    if (act && hl == 0) atomicAdd(&g_pd[r * B + b], p);
                }
            }
        }
        __syncthreads();
    }

    // ---- final reduce + one atomic per pair per CTA ----
    #pragma unroll
    for (int j = 0; j < NJMAX; ++j) {
        const int u = wid + j * 16;
        if (2 * u >= T) continue;
        const int ti = 2 * u + half;
        const int task = s_task[(ti < T) ? ti : (2 * u)];
        const int r   = task >> 8;
        const int off = task & 255;
        const int cnt = s_e[r] - r;
        const bool lv = (ti < T);
        #pragma unroll
        for (int kk = 0; kk < KB; ++kk) {
            float p = acc[j][kk];
            p += __shfl_down_sync(0xFFFFFFFFu, p, 8, 16);
            p += __shfl_down_sync(0xFFFFFFFFu, p, 4, 16);
            p += __shfl_down_sync(0xFFFFFFFFu, p, 2, 16);
            p += __shfl_down_sync(0xFFFFFFFFu, p, 1, 16);
            const int k = off + kk;
            if (lv && (k < cnt) && hl == 0)
                atomicAdd(&g_pd[r * B + (r + k)], p);
        }
    }
}

// =====================================================================
// k2: distances -> dsum -> smoothed normalized weights (slot order)
// =====================================================================
__global__ void k2_weights() {
    __shared__ float sdiag[B];
    __shared__ float swv[B];
    __shared__ float ssum;
    __shared__ int sst[NC + 1];
    int s = threadIdx.x;
    if (s < NC + 1) sst[s] = g_start[s];
    sdiag[s] = g_pd[s * B + s];
    __syncthreads();

    int st = 0, en = 0;
    for (int c = 0; c < NC; ++c)
        if (s >= sst[c] && s < sst[c + 1]) { st = sst[c]; en = sst[c + 1]; }

    float dsum = 0.0f;
    for (int b = st; b < en; ++b) {
        if (b == s) continue;
        float pd = (b >= s) ? g_pd[s * B + b] : g_pd[b * B + s];
        float d2 = sdiag[s] + sdiag[b] - 2.0f * pd;
        dsum += (d2 > 0.0f) ? sqrtf(d2) : 0.0f;
    }
    float w = 1.0f / (sqrtf(dsum * dsum + 25.0f) + 1e-12f);
    swv[s] = w;
    __syncthreads();
    if (s == 0) {
        float S = 0.0f;
        for (int t = 0; t < B; ++t) S += swv[t];
        ssum = S;
    }
    __syncthreads();
    g_wslot[s] = w / (ssum + 1e-12f);
}

// =====================================================================
// k3: weighted class scatter-sum, rolling slot pass, 8-deep prefetch
// =====================================================================
#define PF 8
__global__ void __launch_bounds__(256) k3_scatter(const float* __restrict__ features,
                                                  float* __restrict__ out) {
    __shared__ float sw[B];
    __shared__ int   sm[B];
    __shared__ int   sst[NC + 1];
    int t = threadIdx.x;
    if (t < B)      { sw[t] = g_wslot[t]; sm[t] = g_members[t]; }
    if (t < NC + 1) { sst[t] = g_start[t]; }
    __syncthreads();

    const size_t t4 = (size_t)blockIdx.x * 256 + t;
    const float4* F4 = (const float4*)features;
    float4* O4 = (float4*)out;

    float4 buf[PF];
    #pragma unroll
    for (int k = 0; k < PF; ++k)
        buf[k] = F4[(size_t)sm[k] * D4 + t4];

    int c = 0;
    int nb = sst[1];
    float4 acc = make_float4(0.f, 0.f, 0.f, 0.f);

    for (int s0 = 0; s0 < B; s0 += PF) {
        #pragma unroll
        for (int k = 0; k < PF; ++k) {
            int s = s0 + k;
            while (s == nb && c < NC) {
                O4[(size_t)c * D4 + t4] = acc;
                acc = make_float4(0.f, 0.f, 0.f, 0.f);
                ++c;
                nb = sst[c + 1];
            }
            float4 v = buf[k];
            float w = sw[s];
            acc.x += w * v.x; acc.y += w * v.y;
            acc.z += w * v.z; acc.w += w * v.w;
            int sp = s + PF;
            if (sp < B) buf[k] = F4[(size_t)sm[sp] * D4 + t4];
        }
    }
    while (c < NC) {
        O4[(size_t)c * D4 + t4] = acc;
        acc = make_float4(0.f, 0.f, 0.f, 0.f);
        ++c;
    }
}

// =====================================================================
extern "C" void kernel_launch(void* const* d_in, const int* in_sizes, int n_in,
                              void* d_out, int out_size) {
    const float* features;
    const int*   labels;
    if (in_sizes[0] == B) {
        labels   = (const int*)d_in[0];
        features = (const float*)d_in[1];
    } else {
        features = (const float*)d_in[0];
        labels   = (const int*)d_in[1];
    }
    float* out = (float*)d_out;

    const int k1_smem = 2 * B * KT4 * (int)sizeof(float4);   // 128 KB
    (void)cudaFuncSetAttribute((const void*)k1_pairdots,
                               cudaFuncAttributeMaxDynamicSharedMemorySize,
                               k1_smem);

    k0_prep<<<1, B>>>(labels);
    k1_pairdots<<<NCTA, K1_THREADS, k1_smem>>>(features);
    k2_weights<<<1, B>>>();
    k3_scatter<<<D4 / 256, 256>>>(features, out);
}

// round 6
// speedup vs baseline: 2.9871x; 1.1173x over previous
#include <cuda_runtime.h>
#include <cuda_bf16.h>
#include <math.h>

#define B      128
#define D      524288          // 512*32*32
#define D4     (D/4)           // 131072 float4 per row
#define NC     12
#define KT4    32              // float4 per row per k1 chunk (128 floats)
#define NCHUNK (D4/KT4)        // 4096
#define NCTA   148
#define K1_THREADS 512
#define NJ     5               // register task-slots per warp
#define NU_FAST (16*NJ)        // 80 fast-path tasks
#define NTASK_MAX 1024         // pathological upper bound

// -------- device scratch (no allocation allowed) --------
__device__ float g_pd[B * B];     // pair dots [s][b], s<=b, slot-indexed
__device__ float g_wslot[B];      // normalized weights (slot order)
__device__ int   g_members[B];    // slot -> sample index (class-sorted)
__device__ int   g_start[NC + 1]; // class segment starts (slots)
__device__ int   g_send[B];       // slot -> class end slot
__device__ int   g_tasks[NTASK_MAX]; // (group_start<<8)|partner_off
__device__ int   g_ntasks;

// =====================================================================
// k0: zero pd; class-sort slots; emit (4-row group, 4-partner block)
// tasks. Parallel except tiny serial scans (~200 iters).
// =====================================================================
__global__ void k0_prep(const int* __restrict__ labels) {
    __shared__ int sl[B];
    __shared__ int cstart[NC + 1];
    __shared__ int send_s[B];
    int t = threadIdx.x;
    sl[t] = labels[t];
    for (int p = t; p < B * B; p += B) g_pd[p] = 0.0f;
    __syncthreads();

    if (t == 0) {
        int cnt[NC];
        for (int c = 0; c < NC; ++c) cnt[c] = 0;
        for (int i = 0; i < B; ++i) cnt[sl[i]]++;
        int st = 0;
        for (int c = 0; c < NC; ++c) { cstart[c] = st; st += cnt[c]; }
        cstart[NC] = st;
    }
    __syncthreads();

    // slot of sample t = class start + rank among earlier same-label samples
    {
        int my = sl[t];
        int r = 0;
        for (int j = 0; j < t; ++j) r += (sl[j] == my);
        int slot = cstart[my] + r;
        g_members[slot] = t;
        send_s[slot] = cstart[my + 1];
    }
    if (t < NC + 1) g_start[t] = cstart[t];
    __syncthreads();
    g_send[t] = send_s[t];

    // task emission: per class, 4-row groups x 4-partner blocks
    if (t == 0) {
        int n = 0;
        for (int c = 0; c < NC; ++c) {
            int st = cstart[c], en = cstart[c + 1];
            for (int gs = st; gs < en; gs += 4)
                for (int off = 0; off < en - gs; off += 4)
                    g_tasks[n++] = (gs << 8) | off;
        }
        g_ntasks = n;
    }
}

// =====================================================================
// cp.async helpers
// =====================================================================
__device__ __forceinline__ void cp16(float4* smem_dst, const float4* gmem_src) {
    unsigned s = (unsigned)__cvta_generic_to_shared(smem_dst);
    asm volatile("cp.async.cg.shared.global [%0], [%1], 16;\n" :: "r"(s), "l"(gmem_src));
}
#define CP_COMMIT() asm volatile("cp.async.commit_group;\n" ::: "memory")
#define CP_WAIT1()  asm volatile("cp.async.wait_group 1;\n"  ::: "memory")

__device__ __forceinline__ float dot4(float4 a, float4 b) {
    return a.x * b.x + a.y * b.y + a.z * b.z + a.w * b.w;
}

// =====================================================================
// k1: persistent masked pair dots, 4x4 register-tiled tasks.
// Full warp owns a task: 4 rows x 4 partners, lane owns 1 float4 of the
// 128-float chunk. acc[NJ][16] in registers across all chunks; invalid
// slots computed but never emitted. Reduce + 1 atomic/pair/CTA at end.
// =====================================================================
__global__ void __launch_bounds__(K1_THREADS, 1)
k1_pairdots(const float* __restrict__ features) {
    extern __shared__ float4 S[];          // [2][B*KT4] = 2 x 64 KB
    __shared__ int s_m[B];
    __shared__ int s_e[B];
    __shared__ int s_task[NU_FAST];

    const int tid  = threadIdx.x;
    const int wid  = tid >> 5;
    const int lane = tid & 31;

    if (tid < B) { s_m[tid] = g_members[tid]; s_e[tid] = g_send[tid]; }
    const int T = g_ntasks;
    if (tid < NU_FAST) s_task[tid] = (tid < T) ? g_tasks[tid] : 0;
    __syncthreads();

    const float4* F4 = (const float4*)features;

    auto load_tile = [&](float4* dst, int chunk) {
        const int base4 = chunk * KT4;
        #pragma unroll
        for (int k = 0; k < (B * KT4) / K1_THREADS; ++k) {   // 8
            int idx = tid + k * K1_THREADS;
            int r = idx >> 5, c = idx & 31;
            cp16(&dst[idx], &F4[(size_t)s_m[r] * D4 + base4 + c]);
        }
    };

    float acc[NJ][16];
    #pragma unroll
    for (int j = 0; j < NJ; ++j)
        #pragma unroll
        for (int q = 0; q < 16; ++q) acc[j][q] = 0.0f;

    const bool slow = (T > NU_FAST);

    const int c0 = blockIdx.x;
    if (c0 < NCHUNK) load_tile(S, c0);
    CP_COMMIT();

    int it = 0;
    for (int c = c0; c < NCHUNK; c += NCTA, ++it) {
        int nxt = c + NCTA;
        if (nxt < NCHUNK) load_tile(S + ((it + 1) & 1) * (B * KT4), nxt);
        CP_COMMIT();
        CP_WAIT1();
        __syncthreads();

        const float4* Tb = S + (it & 1) * (B * KT4);

        // ---- fast path: 4x4 register-tiled tasks ----
        #pragma unroll
        for (int j = 0; j < NJ; ++j) {
            const int u = wid + j * 16;
            if (u >= T) continue;                  // warp-uniform
            const int task = s_task[u];
            const int gs  = task >> 8;
            const int off = task & 255;
            const int en  = s_e[gs];
            // 4 row vectors (clamped; invalid rows never emitted)
            float4 a0 = Tb[((gs + 0 < en) ? gs + 0 : gs) * KT4 + lane];
            float4 a1 = Tb[((gs + 1 < en) ? gs + 1 : gs) * KT4 + lane];
            float4 a2 = Tb[((gs + 2 < en) ? gs + 2 : gs) * KT4 + lane];
            float4 a3 = Tb[((gs + 3 < en) ? gs + 3 : gs) * KT4 + lane];
            #pragma unroll
            for (int kk = 0; kk < 4; ++kk) {
                int b = gs + off + kk;
                float4 bv = Tb[((b < en) ? b : gs) * KT4 + lane];
                acc[j][0 * 4 + kk] += dot4(a0, bv);
                acc[j][1 * 4 + kk] += dot4(a1, bv);
                acc[j][2 * 4 + kk] += dot4(a2, bv);
                acc[j][3 * 4 + kk] += dot4(a3, bv);
            }
        }

        // ---- slow path (pathological label skew only) ----
        if (slow) {
            for (int u = NU_FAST + wid; u < T; u += 16) {
                const int task = g_tasks[u];
                const int gs  = task >> 8;
                const int off = task & 255;
                const int en  = s_e[gs];
                #pragma unroll
                for (int jr = 0; jr < 4; ++jr) {
                    int r = gs + jr;
                    if (r >= en) break;
                    float4 a0 = Tb[r * KT4 + lane];
                    for (int kk = 0; kk < 4; ++kk) {
                        int b = gs + off + kk;
                        if (b < r || b >= en) continue;
                        float p = dot4(a0, Tb[b * KT4 + lane]);
                        #pragma unroll
                        for (int o = 16; o > 0; o >>= 1)
                            p += __shfl_down_sync(0xFFFFFFFFu, p, o);
                        if (lane == 0) atomicAdd(&g_pd[r * B + b], p);
                    }
                }
            }
        }
        __syncthreads();
    }

    // ---- final reduce + one atomic per valid pair per CTA ----
    #pragma unroll
    for (int j = 0; j < NJ; ++j) {
        const int u = wid + j * 16;
        if (u >= T) continue;
        const int task = s_task[u];
        const int gs  = task >> 8;
        const int off = task & 255;
        const int en  = s_e[gs];
        #pragma unroll
        for (int jr = 0; jr < 4; ++jr) {
            #pragma unroll
            for (int kk = 0; kk < 4; ++kk) {
                float p = acc[j][jr * 4 + kk];
                #pragma unroll
                for (int o = 16; o > 0; o >>= 1)
                    p += __shfl_down_sync(0xFFFFFFFFu, p, o);
                int r = gs + jr;
                int b = gs + off + kk;
                if (lane == 0 && r < en && b < en && b >= r)
                    atomicAdd(&g_pd[r * B + b], p);
            }
        }
    }
}

// =====================================================================
// k2: distances -> dsum -> smoothed normalized weights (slot order)
// =====================================================================
__global__ void k2_weights() {
    __shared__ float sdiag[B];
    __shared__ float swv[B];
    __shared__ float ssum;
    __shared__ int sst[NC + 1];
    int s = threadIdx.x;
    if (s < NC + 1) sst[s] = g_start[s];
    sdiag[s] = g_pd[s * B + s];
    __syncthreads();

    int st = 0, en = 0;
    for (int c = 0; c < NC; ++c)
        if (s >= sst[c] && s < sst[c + 1]) { st = sst[c]; en = sst[c + 1]; }

    float dsum = 0.0f;
    for (int b = st; b < en; ++b) {
        if (b == s) continue;
        float pd = (b >= s) ? g_pd[s * B + b] : g_pd[b * B + s];
        float d2 = sdiag[s] + sdiag[b] - 2.0f * pd;
        dsum += (d2 > 0.0f) ? sqrtf(d2) : 0.0f;
    }
    float w = 1.0f / (sqrtf(dsum * dsum + 25.0f) + 1e-12f);
    swv[s] = w;
    __syncthreads();
    if (s == 0) {
        float S = 0.0f;
        for (int t = 0; t < B; ++t) S += swv[t];
        ssum = S;
    }
    __syncthreads();
    g_wslot[s] = w / (ssum + 1e-12f);
}

// =====================================================================
// k3: weighted class scatter-sum, rolling slot pass, 8-deep prefetch
// =====================================================================
#define PF 8
__global__ void __launch_bounds__(256) k3_scatter(const float* __restrict__ features,
                                                  float* __restrict__ out) {
    __shared__ float sw[B];
    __shared__ int   sm[B];
    __shared__ int   sst[NC + 1];
    int t = threadIdx.x;
    if (t < B)      { sw[t] = g_wslot[t]; sm[t] = g_members[t]; }
    if (t < NC + 1) { sst[t] = g_start[t]; }
    __syncthreads();

    const size_t t4 = (size_t)blockIdx.x * 256 + t;
    const float4* F4 = (const float4*)features;
    float4* O4 = (float4*)out;

    float4 buf[PF];
    #pragma unroll
    for (int k = 0; k < PF; ++k)
        buf[k] = F4[(size_t)sm[k] * D4 + t4];

    int c = 0;
    int nb = sst[1];
    float4 acc = make_float4(0.f, 0.f, 0.f, 0.f);

    for (int s0 = 0; s0 < B; s0 += PF) {
        #pragma unroll
        for (int k = 0; k < PF; ++k) {
            int s = s0 + k;
            while (s == nb && c < NC) {
                O4[(size_t)c * D4 + t4] = acc;
                acc = make_float4(0.f, 0.f, 0.f, 0.f);
                ++c;
                nb = sst[c + 1];
            }
            float4 v = buf[k];
            float w = sw[s];
            acc.x += w * v.x; acc.y += w * v.y;
            acc.z += w * v.z; acc.w += w * v.w;
            int sp = s + PF;
            if (sp < B) buf[k] = F4[(size_t)sm[sp] * D4 + t4];
        }
    }
    while (c < NC) {
        O4[(size_t)c * D4 + t4] = acc;
        acc = make_float4(0.f, 0.f, 0.f, 0.f);
        ++c;
    }
}

// =====================================================================
extern "C" void kernel_launch(void* const* d_in, const int* in_sizes, int n_in,
                              void* d_out, int out_size) {
    const float* features;
    const int*   labels;
    if (in_sizes[0] == B) {
        labels   = (const int*)d_in[0];
        features = (const float*)d_in[1];
    } else {
        features = (const float*)d_in[0];
        labels   = (const int*)d_in[1];
    }
    float* out = (float*)d_out;

    const int k1_smem = 2 * B * KT4 * (int)sizeof(float4);   // 128 KB
    (void)cudaFuncSetAttribute((const void*)k1_pairdots,
                               cudaFuncAttributeMaxDynamicSharedMemorySize,
                               k1_smem);

    k0_prep<<<1, B>>>(labels);
    k1_pairdots<<<NCTA, K1_THREADS, k1_smem>>>(features);
    k2_weights<<<1, B>>>();
    k3_scatter<<<D4 / 256, 256>>>(features, out);
}

// round 8
// speedup vs baseline: 3.1113x; 1.0416x over previous
#include <cuda_runtime.h>
#include <cuda_bf16.h>
#include <math.h>
#include <stdint.h>

#define B      128
#define D      524288          // 512*32*32
#define D4     (D/4)           // 131072 float4 per row
#define NC     12
#define KT     128             // floats per row per chunk
#define NCHUNK (D/KT)          // 4096
#define NCTA   148
#define K1_THREADS 512

// dynamic smem layout (bytes)
#define STG0   0
#define STG1   65536
#define TILE   131072
#define TP     136             // bf16 tile row pitch (128 + 8 pad)
#define SMEM_DYN (TILE + B * TP * 2)   // 128K + 34816

// -------- device scratch --------
__device__ float g_pd[B * B];     // Gram (same-class entries used), slot-indexed
__device__ float g_wslot[B];
__device__ int   g_members[B];    // slot -> sample index
__device__ int   g_start[NC + 1];
__device__ int   g_cs[B];         // slot -> class start
__device__ int   g_ce[B];         // slot -> class end

// =====================================================================
// k0: zero pd; class-sort slots
// =====================================================================
__global__ void k0_prep(const int* __restrict__ labels) {
    __shared__ int sl[B];
    __shared__ int cstart[NC + 1];
    int t = threadIdx.x;
    sl[t] = labels[t];
    for (int p = t; p < B * B; p += B) g_pd[p] = 0.0f;
    __syncthreads();
    if (t == 0) {
        int cnt[NC];
        for (int c = 0; c < NC; ++c) cnt[c] = 0;
        for (int i = 0; i < B; ++i) cnt[sl[i]]++;
        int st = 0;
        for (int c = 0; c < NC; ++c) { cstart[c] = st; st += cnt[c]; }
        cstart[NC] = st;
    }
    __syncthreads();
    {
        int my = sl[t];
        int r = 0;
        for (int j = 0; j < t; ++j) r += (sl[j] == my);
        int slot = cstart[my] + r;
        g_members[slot] = t;
        g_cs[slot] = cstart[my];
        g_ce[slot] = cstart[my + 1];
    }
    if (t < NC + 1) g_start[t] = cstart[t];
}

// =====================================================================
// PTX helpers (base-ISA only: cp.async, ldmatrix, mma.sync)
// =====================================================================
__device__ __forceinline__ void cp16(void* smem_dst, const void* gmem_src) {
    unsigned s = (unsigned)__cvta_generic_to_shared(smem_dst);
    asm volatile("cp.async.cg.shared.global [%0], [%1], 16;\n" :: "r"(s), "l"(gmem_src));
}
#define CP_COMMIT() asm volatile("cp.async.commit_group;\n" ::: "memory")
#define CP_WAIT1()  asm volatile("cp.async.wait_group 1;\n"  ::: "memory")

__device__ __forceinline__ void ldsm4(uint32_t& r0, uint32_t& r1, uint32_t& r2,
                                      uint32_t& r3, uint32_t addr) {
    asm volatile("ldmatrix.sync.aligned.m8n8.x4.shared.b16 {%0,%1,%2,%3}, [%4];"
                 : "=r"(r0), "=r"(r1), "=r"(r2), "=r"(r3) : "r"(addr));
}
__device__ __forceinline__ void mma16816(float* c, uint32_t a0, uint32_t a1,
                                         uint32_t a2, uint32_t a3,
                                         uint32_t b0, uint32_t b1) {
    asm volatile(
        "mma.sync.aligned.m16n8k16.row.col.f32.bf16.bf16.f32 "
        "{%0,%1,%2,%3}, {%4,%5,%6,%7}, {%8,%9}, {%0,%1,%2,%3};"
        : "+f"(c[0]), "+f"(c[1]), "+f"(c[2]), "+f"(c[3])
        : "r"(a0), "r"(a1), "r"(a2), "r"(a3), "r"(b0), "r"(b1));
}

// =====================================================================
// k1: persistent bf16 mma.sync Gram, split-K. Per chunk: cp.async stage
// fp32 (double-buffered) -> convert to bf16 padded tile -> full 128x128
// HMMA Gram step accumulated in registers across chunks. Epilogue:
// masked atomicAdd of same-class entries.
// =====================================================================
__global__ void __launch_bounds__(K1_THREADS, 1)
k1_gram(const float* __restrict__ features) {
    extern __shared__ char smem[];
    __shared__ int s_m[B];
    __shared__ int s_cs[B], s_ce[B];

    const int tid  = threadIdx.x;
    const int wid  = tid >> 5;
    const int lane = tid & 31;

    if (tid < B) {
        s_m[tid]  = g_members[tid];
        s_cs[tid] = g_cs[tid];
        s_ce[tid] = g_ce[tid];
    }
    __syncthreads();

    const float4* F4 = (const float4*)features;
    const uint32_t tile_sh = (uint32_t)__cvta_generic_to_shared(smem + TILE);

    auto load_stage = [&](int buf, int chunk) {
        float4* dst = (float4*)(smem + (buf ? STG1 : STG0));
        const int base4 = chunk * (KT / 4);
        #pragma unroll
        for (int k = 0; k < (B * KT / 4) / K1_THREADS; ++k) {  // 8
            int idx = tid + k * K1_THREADS;
            int r = idx >> 5, c = idx & 31;
            cp16(&dst[idx], &F4[(size_t)s_m[r] * D4 + base4 + c]);
        }
    };

    // ---- convert mapping: thread -> (row cr, 32-col quarter cq) ----
    const int cr = tid >> 2;
    const int cq = tid & 3;

    // ---- mma mapping: warp = (m-strip, n-half) ----
    const int strip = wid & 7;         // rows strip*16 .. +15
    const int nh    = wid >> 3;        // cols nh*64 .. +63
    const int m0    = strip * 16;

    // A ldmatrix lane address parts (row-major m16k16)
    const int a_row = m0 + (lane & 7) + ((lane >> 3) & 1) * 8;
    const int a_col8 = (lane >> 4) * 8;
    // B ldmatrix lane address parts (n-major n16k16 -> frag pair order)
    const int b_rowoff = (lane & 7) + ((lane >> 4) & 1) * 8;  // n within 16
    const int b_col8   = ((lane >> 3) & 1) * 8;               // k 0 / 8

    float acc[8][4];
    #pragma unroll
    for (int t = 0; t < 8; ++t)
        #pragma unroll
        for (int q = 0; q < 4; ++q) acc[t][q] = 0.0f;

    const int c0 = blockIdx.x;
    load_stage(0, c0);
    CP_COMMIT();

    int it = 0;
    for (int c = c0; c < NCHUNK; c += NCTA, ++it) {
        int nxt = c + NCTA;
        if (nxt < NCHUNK) load_stage((it + 1) & 1, nxt);
        CP_COMMIT();
        CP_WAIT1();
        __syncthreads();

        // ---- fp32 stage -> bf16 tile [128][TP] ----
        {
            const float4* S4 = (const float4*)(smem + ((it & 1) ? STG1 : STG0));
            const float4* row = S4 + cr * 32 + cq * 8;
            __nv_bfloat162* trow = (__nv_bfloat162*)(smem + TILE) + (cr * TP + cq * 32) / 2;
            #pragma unroll
            for (int k = 0; k < 4; ++k) {
                int kk = (k + cq) & 3;          // stagger to avoid STS conflicts
                float4 f0 = row[2 * kk];
                float4 f1 = row[2 * kk + 1];
                __nv_bfloat162 h0 = __float22bfloat162_rn(make_float2(f0.x, f0.y));
                __nv_bfloat162 h1 = __float22bfloat162_rn(make_float2(f0.z, f0.w));
                __nv_bfloat162 h2 = __float22bfloat162_rn(make_float2(f1.x, f1.y));
                __nv_bfloat162 h3 = __float22bfloat162_rn(make_float2(f1.z, f1.w));
                uint4 v;
                v.x = *(uint32_t*)&h0; v.y = *(uint32_t*)&h1;
                v.z = *(uint32_t*)&h2; v.w = *(uint32_t*)&h3;
                *(uint4*)(trow + kk * 4) = v;
            }
        }
        __syncthreads();

        // ---- HMMA: 8 k-steps, strip x n64 per warp ----
        #pragma unroll
        for (int ks = 0; ks < 8; ++ks) {
            const int k0 = ks * 16;
            uint32_t a0, a1, a2, a3;
            ldsm4(a0, a1, a2, a3,
                  tile_sh + (uint32_t)(a_row * TP + k0 + a_col8) * 2);
            #pragma unroll
            for (int bt = 0; bt < 4; ++bt) {
                const int n0 = nh * 64 + bt * 16;
                uint32_t b0, b1, b2, b3;
                ldsm4(b0, b1, b2, b3,
                      tile_sh + (uint32_t)((n0 + b_rowoff) * TP + k0 + b_col8) * 2);
                mma16816(acc[2 * bt],     a0, a1, a2, a3, b0, b1);
                mma16816(acc[2 * bt + 1], a0, a1, a2, a3, b2, b3);
            }
        }
        __syncthreads();                // tile reuse fence
    }

    // ---- epilogue: masked atomicAdd of same-class Gram entries ----
    {
        const int gid = lane >> 2;
        const int tig = lane & 3;
        const int r0 = m0 + gid, r1 = m0 + gid + 8;
        const int cs0 = s_cs[r0], ce0 = s_ce[r0];
        const int cs1 = s_cs[r1], ce1 = s_ce[r1];
        #pragma unroll
        for (int t = 0; t < 8; ++t) {
            const int cA = nh * 64 + t * 8 + tig * 2;
            const int cBc = cA + 1;
            if (cA  >= cs0 && cA  < ce0) atomicAdd(&g_pd[r0 * B + cA],  acc[t][0]);
            if (cBc >= cs0 && cBc < ce0) atomicAdd(&g_pd[r0 * B + cBc], acc[t][1]);
            if (cA  >= cs1 && cA  < ce1) atomicAdd(&g_pd[r1 * B + cA],  acc[t][2]);
            if (cBc >= cs1 && cBc < ce1) atomicAdd(&g_pd[r1 * B + cBc], acc[t][3]);
        }
    }
}

// =====================================================================
// k2: distances -> dsum -> smoothed normalized weights
// =====================================================================
__global__ void k2_weights() {
    __shared__ float sdiag[B];
    __shared__ float swv[B];
    __shared__ float ssum;
    int s = threadIdx.x;
    sdiag[s] = g_pd[s * B + s];
    int st = g_cs[s], en = g_ce[s];
    __syncthreads();

    float dsum = 0.0f;
    for (int b = st; b < en; ++b) {
        if (b == s) continue;
        float d2 = sdiag[s] + sdiag[b] - 2.0f * g_pd[s * B + b];
        dsum += (d2 > 0.0f) ? sqrtf(d2) : 0.0f;
    }
    float w = 1.0f / (sqrtf(dsum * dsum + 25.0f) + 1e-12f);
    swv[s] = w;
    __syncthreads();
    if (s == 0) {
        float S = 0.0f;
        for (int t = 0; t < B; ++t) S += swv[t];
        ssum = S;
    }
    __syncthreads();
    g_wslot[s] = w / (ssum + 1e-12f);
}

// =====================================================================
// k3: weighted class scatter-sum (unchanged, DRAM ~79%)
// =====================================================================
#define PF 8
__global__ void __launch_bounds__(256) k3_scatter(const float* __restrict__ features,
                                                  float* __restrict__ out) {
    __shared__ float sw[B];
    __shared__ int   sm[B];
    __shared__ int   sst[NC + 1];
    int t = threadIdx.x;
    if (t < B)      { sw[t] = g_wslot[t]; sm[t] = g_members[t]; }
    if (t < NC + 1) { sst[t] = g_start[t]; }
    __syncthreads();

    const size_t t4 = (size_t)blockIdx.x * 256 + t;
    const float4* F4 = (const float4*)features;
    float4* O4 = (float4*)out;

    float4 buf[PF];
    #pragma unroll
    for (int k = 0; k < PF; ++k)
        buf[k] = F4[(size_t)sm[k] * D4 + t4];

    int c = 0;
    int nb = sst[1];
    float4 acc = make_float4(0.f, 0.f, 0.f, 0.f);

    for (int s0 = 0; s0 < B; s0 += PF) {
        #pragma unroll
        for (int k = 0; k < PF; ++k) {
            int s = s0 + k;
            while (s == nb && c < NC) {
                O4[(size_t)c * D4 + t4] = acc;
                acc = make_float4(0.f, 0.f, 0.f, 0.f);
                ++c;
                nb = sst[c + 1];
            }
            float4 v = buf[k];
            float w = sw[s];
            acc.x += w * v.x; acc.y += w * v.y;
            acc.z += w * v.z; acc.w += w * v.w;
            int sp = s + PF;
            if (sp < B) buf[k] = F4[(size_t)sm[sp] * D4 + t4];
        }
    }
    while (c < NC) {
        O4[(size_t)c * D4 + t4] = acc;
        acc = make_float4(0.f, 0.f, 0.f, 0.f);
        ++c;
    }
}

// =====================================================================
extern "C" void kernel_launch(void* const* d_in, const int* in_sizes, int n_in,
                              void* d_out, int out_size) {
    const float* features;
    const int*   labels;
    if (in_sizes[0] == B) {
        labels   = (const int*)d_in[0];
        features = (const float*)d_in[1];
    } else {
        features = (const float*)d_in[0];
        labels   = (const int*)d_in[1];
    }
    float* out = (float*)d_out;

    (void)cudaFuncSetAttribute((const void*)k1_gram,
                               cudaFuncAttributeMaxDynamicSharedMemorySize,
                               SMEM_DYN);

    k0_prep<<<1, B>>>(labels);
    k1_gram<<<NCTA, K1_THREADS, SMEM_DYN>>>(features);
    k2_weights<<<1, B>>>();
    k3_scatter<<<D4 / 256, 256>>>(features, out);
}

// round 10
// speedup vs baseline: 3.2174x; 1.0341x over previous
#include <cuda_runtime.h>
#include <cuda_bf16.h>
#include <math.h>
#include <stdint.h>

#define B      128
#define D      524288          // 512*32*32
#define D4     (D/4)           // 131072 float4 per row
#define NC     12
#define KT     128             // floats per row per chunk
#define NCHUNK (D/KT)          // 4096
#define NCTA   148
#define K1_THREADS 512

// dynamic smem layout (bytes)
#define STG0   0
#define STG1   65536
#define TP     136             // bf16 tile row pitch (128 + 8 pad)
#define TILE0  131072
#define TILE1  (TILE0 + B * TP * 2)
#define SMEM_DYN (TILE1 + B * TP * 2)   // 200704

// -------- device scratch --------
__device__ float g_pd[B * B];     // Gram (same-class entries used), slot-indexed
__device__ float g_wslot[B];
__device__ int   g_members[B];    // slot -> sample index
__device__ int   g_start[NC + 1];
__device__ int   g_cs[B];         // slot -> class start
__device__ int   g_ce[B];         // slot -> class end
__device__ int   g_band0[8];      // per 16-row strip: band start col (clamped)
__device__ int   g_ntile;         // 16-col tiles per warp (2 banded / 4 full)

// =====================================================================
// k0: zero pd; class-sort slots; per-strip band bounds (CLAMPED so the
// 64-col band never exceeds column 128)
// =====================================================================
__global__ void k0_prep(const int* __restrict__ labels) {
    __shared__ int sl[B];
    __shared__ int cstart[NC + 1];
    int t = threadIdx.x;
    sl[t] = labels[t];
    for (int p = t; p < B * B; p += B) g_pd[p] = 0.0f;
    __syncthreads();
    if (t == 0) {
        int cnt[NC];
        for (int c = 0; c < NC; ++c) cnt[c] = 0;
        for (int i = 0; i < B; ++i) cnt[sl[i]]++;
        int st = 0;
        for (int c = 0; c < NC; ++c) { cstart[c] = st; st += cnt[c]; }
        cstart[NC] = st;
    }
    __syncthreads();
    {
        int my = sl[t];
        int r = 0;
        for (int j = 0; j < t; ++j) r += (sl[j] == my);
        int slot = cstart[my] + r;
        g_members[slot] = t;
        g_cs[slot] = cstart[my];
        g_ce[slot] = cstart[my + 1];
    }
    if (t < NC + 1) g_start[t] = cstart[t];
    __syncthreads();
    if (t == 0) {
        int wide = 0;
        int b0[8];
        for (int s = 0; s < 8; ++s) {
            int nb0 = g_cs[16 * s] & ~7;
            if (nb0 > B - 64) nb0 = B - 64;        // clamp: band end <= 128
            b0[s] = nb0;
            if (g_ce[16 * s + 15] - nb0 > 64) wide = 1;
        }
        for (int s = 0; s < 8; ++s) g_band0[s] = wide ? 0 : b0[s];
        g_ntile = wide ? 4 : 2;
    }
}

// =====================================================================
// PTX helpers (base-ISA only: cp.async, ldmatrix, mma.sync)
// =====================================================================
__device__ __forceinline__ void cp16(void* smem_dst, const void* gmem_src) {
    unsigned s = (unsigned)__cvta_generic_to_shared(smem_dst);
    asm volatile("cp.async.cg.shared.global [%0], [%1], 16;\n" :: "r"(s), "l"(gmem_src));
}
#define CP_COMMIT() asm volatile("cp.async.commit_group;\n" ::: "memory")
#define CP_WAIT1()  asm volatile("cp.async.wait_group 1;\n"  ::: "memory")

__device__ __forceinline__ void ldsm4(uint32_t& r0, uint32_t& r1, uint32_t& r2,
                                      uint32_t& r3, uint32_t addr) {
    asm volatile("ldmatrix.sync.aligned.m8n8.x4.shared.b16 {%0,%1,%2,%3}, [%4];"
                 : "=r"(r0), "=r"(r1), "=r"(r2), "=r"(r3) : "r"(addr));
}
__device__ __forceinline__ void mma16816(float* c, uint32_t a0, uint32_t a1,
                                         uint32_t a2, uint32_t a3,
                                         uint32_t b0, uint32_t b1) {
    asm volatile(
        "mma.sync.aligned.m16n8k16.row.col.f32.bf16.bf16.f32 "
        "{%0,%1,%2,%3}, {%4,%5,%6,%7}, {%8,%9}, {%0,%1,%2,%3};"
        : "+f"(c[0]), "+f"(c[1]), "+f"(c[2]), "+f"(c[3])
        : "r"(a0), "r"(a1), "r"(a2), "r"(a3), "r"(b0), "r"(b1));
}

// =====================================================================
// k1: persistent bf16 mma.sync BANDED Gram, split-K. Per chunk: cp.async
// fp32 stage (double-buffered) -> convert to bf16 tile (double-buffered)
// -> per-strip banded HMMA accumulated in registers across chunks.
// ONE barrier per chunk. Epilogue: masked atomicAdd of same-class cells.
// =====================================================================
__global__ void __launch_bounds__(K1_THREADS, 1)
k1_gram(const float* __restrict__ features) {
    extern __shared__ char smem[];
    __shared__ int s_m[B];
    __shared__ int s_cs[B], s_ce[B];
    __shared__ int s_b0[8];
    __shared__ int s_nt;

    const int tid  = threadIdx.x;
    const int wid  = tid >> 5;
    const int lane = tid & 31;

    if (tid < B) {
        s_m[tid]  = g_members[tid];
        s_cs[tid] = g_cs[tid];
        s_ce[tid] = g_ce[tid];
    }
    if (tid < 8) s_b0[tid] = g_band0[tid];
    if (tid == 0) s_nt = g_ntile;
    __syncthreads();

    const float4* F4 = (const float4*)features;
    const int ntile = s_nt;                       // 2 banded / 4 full

    auto load_stage = [&](int buf, int chunk) {
        float4* dst = (float4*)(smem + (buf ? STG1 : STG0));
        const int base4 = chunk * (KT / 4);
        #pragma unroll
        for (int k = 0; k < (B * KT / 4) / K1_THREADS; ++k) {  // 8
            int idx = tid + k * K1_THREADS;
            int r = idx >> 5, c = idx & 31;
            cp16(&dst[idx], &F4[(size_t)s_m[r] * D4 + base4 + c]);
        }
    };

    // ---- convert mapping: thread -> (row cr, 32-col quarter cq) ----
    const int cr = tid >> 2;
    const int cq = tid & 3;

    // ---- mma mapping: warp = (strip, band half) ----
    const int strip = wid >> 1;
    const int half  = wid & 1;
    const int m0    = strip * 16;
    const int wbase = s_b0[strip] + half * ntile * 16;

    // ldmatrix lane address parts
    const int a_row  = m0 + (lane & 7) + ((lane >> 3) & 1) * 8;
    const int a_col8 = (lane >> 4) * 8;
    const int b_rowoff = (lane & 7) + ((lane >> 4) & 1) * 8;
    const int b_col8   = ((lane >> 3) & 1) * 8;

    float acc[4][8];
    #pragma unroll
    for (int t = 0; t < 4; ++t)
        #pragma unroll
        for (int q = 0; q < 8; ++q) acc[t][q] = 0.0f;

    const int c0 = blockIdx.x;
    load_stage(0, c0);
    CP_COMMIT();

    int it = 0;
    for (int c = c0; c < NCHUNK; c += NCTA, ++it) {
        int nxt = c + NCTA;
        if (nxt < NCHUNK) load_stage((it + 1) & 1, nxt);
        CP_COMMIT();
        CP_WAIT1();                       // stage[it&1] complete

        char* tilep = smem + ((it & 1) ? TILE1 : TILE0);
        const uint32_t tile_sh = (uint32_t)__cvta_generic_to_shared(tilep);

        // ---- fp32 stage -> bf16 tile[it&1] ----
        {
            const float4* S4 = (const float4*)(smem + ((it & 1) ? STG1 : STG0));
            const float4* row = S4 + cr * 32 + cq * 8;
            #pragma unroll
            for (int k = 0; k < 4; ++k) {
                int kk = (k + cq) & 3;
                float4 f0 = row[2 * kk];
                float4 f1 = row[2 * kk + 1];
                __nv_bfloat162 h0 = __float22bfloat162_rn(make_float2(f0.x, f0.y));
                __nv_bfloat162 h1 = __float22bfloat162_rn(make_float2(f0.z, f0.w));
                __nv_bfloat162 h2 = __float22bfloat162_rn(make_float2(f1.x, f1.y));
                __nv_bfloat162 h3 = __float22bfloat162_rn(make_float2(f1.z, f1.w));
                uint4 v;
                v.x = *(uint32_t*)&h0; v.y = *(uint32_t*)&h1;
                v.z = *(uint32_t*)&h2; v.w = *(uint32_t*)&h3;
                *(uint4*)(tilep + (cr * TP + cq * 32 + kk * 8) * 2) = v;
            }
        }
        __syncthreads();                  // tile[it&1] visible to all warps

        // ---- banded HMMA: 8 k-steps x ntile 16-col tiles ----
        #pragma unroll
        for (int ks = 0; ks < 8; ++ks) {
            const int k0c = ks * 16;
            uint32_t a0, a1, a2, a3;
            ldsm4(a0, a1, a2, a3,
                  tile_sh + (uint32_t)(a_row * TP + k0c + a_col8) * 2);
            #pragma unroll
            for (int nt = 0; nt < 4; ++nt) {
                if (nt < ntile) {         // warp-uniform guard
                    const int n0 = wbase + nt * 16;
                    uint32_t b0, b1, b2, b3;
                    ldsm4(b0, b1, b2, b3,
                          tile_sh + (uint32_t)((n0 + b_rowoff) * TP + k0c + b_col8) * 2);
                    mma16816(&acc[nt][0], a0, a1, a2, a3, b0, b1);
                    mma16816(&acc[nt][4], a0, a1, a2, a3, b2, b3);
                }
            }
        }
        // no second barrier: next iter converts into the OTHER tile buffer
    }

    // ---- epilogue: masked atomicAdd of same-class Gram entries ----
    {
        const int gid = lane >> 2;
        const int tig = lane & 3;
        const int r0 = m0 + gid, r1 = m0 + gid + 8;
        const int cs0 = s_cs[r0], ce0 = s_ce[r0];
        const int cs1 = s_cs[r1], ce1 = s_ce[r1];
        #pragma unroll
        for (int nt = 0; nt < 4; ++nt) {
            if (nt < ntile) {
                const int base = wbase + nt * 16;
                const int cA = base + tig * 2,     cB = cA + 1;
                const int cC = base + 8 + tig * 2, cD = cC + 1;
                if (cA >= cs0 && cA < ce0) atomicAdd(&g_pd[r0 * B + cA], acc[nt][0]);
                if (cB >= cs0 && cB < ce0) atomicAdd(&g_pd[r0 * B + cB], acc[nt][1]);
                if (cA >= cs1 && cA < ce1) atomicAdd(&g_pd[r1 * B + cA], acc[nt][2]);
                if (cB >= cs1 && cB < ce1) atomicAdd(&g_pd[r1 * B + cB], acc[nt][3]);
                if (cC >= cs0 && cC < ce0) atomicAdd(&g_pd[r0 * B + cC], acc[nt][4]);
                if (cD >= cs0 && cD < ce0) atomicAdd(&g_pd[r0 * B + cD], acc[nt][5]);
                if (cC >= cs1 && cC < ce1) atomicAdd(&g_pd[r1 * B + cC], acc[nt][6]);
                if (cD >= cs1 && cD < ce1) atomicAdd(&g_pd[r1 * B + cD], acc[nt][7]);
            }
        }
    }
}

// =====================================================================
// k2: distances -> dsum -> smoothed normalized weights
// =====================================================================
__global__ void k2_weights() {
    __shared__ float sdiag[B];
    __shared__ float swv[B];
    __shared__ float ssum;
    int s = threadIdx.x;
    sdiag[s] = g_pd[s * B + s];
    int st = g_cs[s], en = g_ce[s];
    __syncthreads();

    float dsum = 0.0f;
    for (int b = st; b < en; ++b) {
        if (b == s) continue;
        float d2 = sdiag[s] + sdiag[b] - 2.0f * g_pd[s * B + b];
        dsum += (d2 > 0.0f) ? sqrtf(d2) : 0.0f;
    }
    float w = 1.0f / (sqrtf(dsum * dsum + 25.0f) + 1e-12f);
    swv[s] = w;
    __syncthreads();
    if (s == 0) {
        float S = 0.0f;
        for (int t = 0; t < B; ++t) S += swv[t];
        ssum = S;
    }
    __syncthreads();
    g_wslot[s] = w / (ssum + 1e-12f);
}

// =====================================================================
// k3: weighted class scatter-sum (unchanged, DRAM ~79%)
// =====================================================================
#define PF 8
__global__ void __launch_bounds__(256) k3_scatter(const float* __restrict__ features,
                                                  float* __restrict__ out) {
    __shared__ float sw[B];
    __shared__ int   sm[B];
    __shared__ int   sst[NC + 1];
    int t = threadIdx.x;
    if (t < B)      { sw[t] = g_wslot[t]; sm[t] = g_members[t]; }
    if (t < NC + 1) { sst[t] = g_start[t]; }
    __syncthreads();

    const size_t t4 = (size_t)blockIdx.x * 256 + t;
    const float4* F4 = (const float4*)features;
    float4* O4 = (float4*)out;

    float4 buf[PF];
    #pragma unroll
    for (int k = 0; k < PF; ++k)
        buf[k] = F4[(size_t)sm[k] * D4 + t4];

    int c = 0;
    int nb = sst[1];
    float4 acc = make_float4(0.f, 0.f, 0.f, 0.f);

    for (int s0 = 0; s0 < B; s0 += PF) {
        #pragma unroll
        for (int k = 0; k < PF; ++k) {
            int s = s0 + k;
            while (s == nb && c < NC) {
                O4[(size_t)c * D4 + t4] = acc;
                acc = make_float4(0.f, 0.f, 0.f, 0.f);
                ++c;
                nb = sst[c + 1];
            }
            float4 v = buf[k];
            float w = sw[s];
            acc.x += w * v.x; acc.y += w * v.y;
            acc.z += w * v.z; acc.w += w * v.w;
            int sp = s + PF;
            if (sp < B) buf[k] = F4[(size_t)sm[sp] * D4 + t4];
        }
    }
    while (c < NC) {
        O4[(size_t)c * D4 + t4] = acc;
        acc = make_float4(0.f, 0.f, 0.f, 0.f);
        ++c;
    }
}

// =====================================================================
extern "C" void kernel_launch(void* const* d_in, const int* in_sizes, int n_in,
                              void* d_out, int out_size) {
    const float* features;
    const int*   labels;
    if (in_sizes[0] == B) {
        labels   = (const int*)d_in[0];
        features = (const float*)d_in[1];
    } else {
        features = (const float*)d_in[0];
        labels   = (const int*)d_in[1];
    }
    float* out = (float*)d_out;

    (void)cudaFuncSetAttribute((const void*)k1_gram,
                               cudaFuncAttributeMaxDynamicSharedMemorySize,
                               SMEM_DYN);

    k0_prep<<<1, B>>>(labels);
    k1_gram<<<NCTA, K1_THREADS, SMEM_DYN>>>(features);
    k2_weights<<<1, B>>>();
    k3_scatter<<<D4 / 256, 256>>>(features, out);
}

// round 11
// speedup vs baseline: 3.7197x; 1.1561x over previous
#include <cuda_runtime.h>
#include <cuda_bf16.h>
#include <math.h>
#include <stdint.h>

#define B      128
#define D      524288          // 512*32*32
#define D4     (D/4)           // 131072 float4 per row
#define NC     12
#define KT     128             // floats per row per chunk
#define NCHUNK (D/KT)          // 4096
#define NCTA2  296             // 2 CTAs per SM
#define K1_THREADS 512

// dynamic smem: two bf16 tiles [B][TP]
#define TP     136             // bf16 tile row pitch (128 + 8 pad)
#define TILE0  0
#define TILE1  (B * TP * 2)
#define SMEM_DYN (2 * B * TP * 2)   // 69632

// -------- device scratch --------
__device__ float g_pd[B * B];     // Gram (same-class entries used), slot-indexed
__device__ float g_wslot[B];
__device__ int   g_members[B];    // slot -> sample index
__device__ int   g_start[NC + 1];
__device__ int   g_cs[B];         // slot -> class start
__device__ int   g_ce[B];         // slot -> class end
__device__ int   g_band0[8];      // per 16-row strip: band start col (clamped)
__device__ int   g_ntile;         // 2 = banded (64-wide), 4 = wide fallback

// =====================================================================
// k0: zero pd; class-sort slots; per-strip clamped band bounds
// =====================================================================
__global__ void k0_prep(const int* __restrict__ labels) {
    __shared__ int sl[B];
    __shared__ int cstart[NC + 1];
    int t = threadIdx.x;
    sl[t] = labels[t];
    for (int p = t; p < B * B; p += B) g_pd[p] = 0.0f;
    __syncthreads();
    if (t == 0) {
        int cnt[NC];
        for (int c = 0; c < NC; ++c) cnt[c] = 0;
        for (int i = 0; i < B; ++i) cnt[sl[i]]++;
        int st = 0;
        for (int c = 0; c < NC; ++c) { cstart[c] = st; st += cnt[c]; }
        cstart[NC] = st;
    }
    __syncthreads();
    {
        int my = sl[t];
        int r = 0;
        for (int j = 0; j < t; ++j) r += (sl[j] == my);
        int slot = cstart[my] + r;
        g_members[slot] = t;
        g_cs[slot] = cstart[my];
        g_ce[slot] = cstart[my + 1];
    }
    if (t < NC + 1) g_start[t] = cstart[t];
    __syncthreads();
    if (t == 0) {
        int wide = 0;
        int b0[8];
        for (int s = 0; s < 8; ++s) {
            int nb0 = g_cs[16 * s] & ~7;
            if (nb0 > B - 64) nb0 = B - 64;        // band end <= 128
            b0[s] = nb0;
            if (g_ce[16 * s + 15] - nb0 > 64) wide = 1;
        }
        for (int s = 0; s < 8; ++s) g_band0[s] = wide ? 0 : b0[s];
        g_ntile = wide ? 4 : 2;
    }
}

// =====================================================================
// PTX helpers (base-ISA: ldmatrix, mma.sync)
// =====================================================================
__device__ __forceinline__ void ldsm4(uint32_t& r0, uint32_t& r1, uint32_t& r2,
                                      uint32_t& r3, uint32_t addr) {
    asm volatile("ldmatrix.sync.aligned.m8n8.x4.shared.b16 {%0,%1,%2,%3}, [%4];"
                 : "=r"(r0), "=r"(r1), "=r"(r2), "=r"(r3) : "r"(addr));
}
__device__ __forceinline__ void mma16816(float* c, uint32_t a0, uint32_t a1,
                                         uint32_t a2, uint32_t a3,
                                         uint32_t b0, uint32_t b1) {
    asm volatile(
        "mma.sync.aligned.m16n8k16.row.col.f32.bf16.bf16.f32 "
        "{%0,%1,%2,%3}, {%4,%5,%6,%7}, {%8,%9}, {%0,%1,%2,%3};"
        : "+f"(c[0]), "+f"(c[1]), "+f"(c[2]), "+f"(c[3])
        : "r"(a0), "r"(a1), "r"(a2), "r"(a3), "r"(b0), "r"(b1));
}

// =====================================================================
// k1: persistent banded bf16 mma.sync Gram, 2 CTAs/SM for overlap.
// Per chunk: direct LDG fp32 -> register convert -> STS bf16 into
// double-buffered tile -> one barrier -> banded HMMA into registers.
// Epilogue: one atomicAdd per cell per CTA.
// =====================================================================
__global__ void __launch_bounds__(K1_THREADS, 2)
k1_gram(const float* __restrict__ features) {
    extern __shared__ char smem[];
    __shared__ size_t s_roff[B];     // slot -> row base offset (float4 units)
    __shared__ int s_b0[8];
    __shared__ int s_nt;

    const int tid  = threadIdx.x;
    const int wid  = tid >> 5;
    const int lane = tid & 31;

    if (tid < B) s_roff[tid] = (size_t)g_members[tid] * D4;
    if (tid < 8) s_b0[tid] = g_band0[tid];
    if (tid == 0) s_nt = g_ntile;
    __syncthreads();

    const float4* F4 = (const float4*)features;
    const bool wide = (s_nt == 4);
    const int nseg  = wide ? 2 : 1;

    // ---- mma mapping: warp = (strip, band half) ----
    const int strip = wid >> 1;
    const int half  = wid & 1;
    const int m0    = strip * 16;
    const int wbase = s_b0[strip] + half * (wide ? 64 : 32);

    // ldmatrix lane address parts
    const int a_row    = m0 + (lane & 7) + ((lane >> 3) & 1) * 8;
    const int a_col8   = (lane >> 4) * 8;
    const int b_rowoff = (lane & 7) + ((lane >> 4) & 1) * 8;
    const int b_col8   = ((lane >> 3) & 1) * 8;

    // epilogue cell indices
    const int gid = lane >> 2;
    const int tig = lane & 3;
    const int r0 = m0 + gid, r1 = m0 + gid + 8;

    float acc[2][8];
    #pragma unroll
    for (int t = 0; t < 2; ++t)
        #pragma unroll
        for (int q = 0; q < 8; ++q) acc[t][q] = 0.0f;

    auto flush = [&](int base_n) {
        #pragma unroll
        for (int nt = 0; nt < 2; ++nt) {
            const int base = base_n + nt * 16;
            const int cA = base + tig * 2;
            const int cC = base + 8 + tig * 2;
            atomicAdd(&g_pd[r0 * B + cA],     acc[nt][0]);
            atomicAdd(&g_pd[r0 * B + cA + 1], acc[nt][1]);
            atomicAdd(&g_pd[r1 * B + cA],     acc[nt][2]);
            atomicAdd(&g_pd[r1 * B + cA + 1], acc[nt][3]);
            atomicAdd(&g_pd[r0 * B + cC],     acc[nt][4]);
            atomicAdd(&g_pd[r0 * B + cC + 1], acc[nt][5]);
            atomicAdd(&g_pd[r1 * B + cC],     acc[nt][6]);
            atomicAdd(&g_pd[r1 * B + cC + 1], acc[nt][7]);
        }
    };

    int it = 0;
    for (int c = blockIdx.x; c < NCHUNK; c += NCTA2, ++it) {
        char* tilep = smem + ((it & 1) ? TILE1 : TILE0);
        const uint32_t tile_sh = (uint32_t)__cvta_generic_to_shared(tilep);

        // ---- direct LDG -> convert -> STS (rows wid+16k, float4 col lane) ----
        const size_t base4 = (size_t)c * (KT / 4) + lane;
        #pragma unroll
        for (int h8 = 0; h8 < 2; ++h8) {
            float4 buf[4];
            #pragma unroll
            for (int k = 0; k < 4; ++k) {
                const int row = wid + (h8 * 4 + k) * 16;
                buf[k] = F4[s_roff[row] + base4];
            }
            #pragma unroll
            for (int k = 0; k < 4; ++k) {
                const int row = wid + (h8 * 4 + k) * 16;
                __nv_bfloat162 h0 = __float22bfloat162_rn(make_float2(buf[k].x, buf[k].y));
                __nv_bfloat162 h1 = __float22bfloat162_rn(make_float2(buf[k].z, buf[k].w));
                uint2 v;
                v.x = *(uint32_t*)&h0;
                v.y = *(uint32_t*)&h1;
                *(uint2*)(tilep + row * (TP * 2) + lane * 8) = v;
            }
        }
        __syncthreads();   // tile[it&1] visible; prev-iter HMMA used other buffer

        // ---- banded HMMA (1 segment) / wide fallback (2 segments) ----
        for (int seg = 0; seg < nseg; ++seg) {
            const int seg_base = wbase + seg * 32;
            #pragma unroll
            for (int ks = 0; ks < 8; ++ks) {
                const int k0c = ks * 16;
                uint32_t a0, a1, a2, a3;
                ldsm4(a0, a1, a2, a3,
                      tile_sh + (uint32_t)(a_row * TP + k0c + a_col8) * 2);
                #pragma unroll
                for (int nt = 0; nt < 2; ++nt) {
                    const int n0 = seg_base + nt * 16;
                    uint32_t b0, b1, b2, b3;
                    ldsm4(b0, b1, b2, b3,
                          tile_sh + (uint32_t)((n0 + b_rowoff) * TP + k0c + b_col8) * 2);
                    mma16816(&acc[nt][0], a0, a1, a2, a3, b0, b1);
                    mma16816(&acc[nt][4], a0, a1, a2, a3, b2, b3);
                }
            }
            if (wide) {        // pathological path: flush + rezero each chunk
                flush(seg_base);
                #pragma unroll
                for (int t = 0; t < 2; ++t)
                    #pragma unroll
                    for (int q = 0; q < 8; ++q) acc[t][q] = 0.0f;
            }
        }
    }

    if (!wide) flush(wbase);   // one atomic per cell per CTA
}

// =====================================================================
// k2: distances -> dsum -> smoothed normalized weights
// =====================================================================
__global__ void k2_weights() {
    __shared__ float sdiag[B];
    __shared__ float swv[B];
    __shared__ float ssum;
    int s = threadIdx.x;
    sdiag[s] = g_pd[s * B + s];
    int st = g_cs[s], en = g_ce[s];
    __syncthreads();

    float dsum = 0.0f;
    for (int b = st; b < en; ++b) {
        if (b == s) continue;
        float d2 = sdiag[s] + sdiag[b] - 2.0f * g_pd[s * B + b];
        dsum += (d2 > 0.0f) ? sqrtf(d2) : 0.0f;
    }
    float w = 1.0f / (sqrtf(dsum * dsum + 25.0f) + 1e-12f);
    swv[s] = w;
    __syncthreads();
    if (s == 0) {
        float S = 0.0f;
        for (int t = 0; t < B; ++t) S += swv[t];
        ssum = S;
    }
    __syncthreads();
    g_wslot[s] = w / (ssum + 1e-12f);
}

// =====================================================================
// k3: weighted class scatter-sum (unchanged, ~79% DRAM)
// =====================================================================
#define PF 8
__global__ void __launch_bounds__(256) k3_scatter(const float* __restrict__ features,
                                                  float* __restrict__ out) {
    __shared__ float sw[B];
    __shared__ int   sm[B];
    __shared__ int   sst[NC + 1];
    int t = threadIdx.x;
    if (t < B)      { sw[t] = g_wslot[t]; sm[t] = g_members[t]; }
    if (t < NC + 1) { sst[t] = g_start[t]; }
    __syncthreads();

    const size_t t4 = (size_t)blockIdx.x * 256 + t;
    const float4* F4 = (const float4*)features;
    float4* O4 = (float4*)out;

    float4 buf[PF];
    #pragma unroll
    for (int k = 0; k < PF; ++k)
        buf[k] = F4[(size_t)sm[k] * D4 + t4];

    int c = 0;
    int nb = sst[1];
    float4 acc = make_float4(0.f, 0.f, 0.f, 0.f);

    for (int s0 = 0; s0 < B; s0 += PF) {
        #pragma unroll
        for (int k = 0; k < PF; ++k) {
            int s = s0 + k;
            while (s == nb && c < NC) {
                O4[(size_t)c * D4 + t4] = acc;
                acc = make_float4(0.f, 0.f, 0.f, 0.f);
                ++c;
                nb = sst[c + 1];
            }
            float4 v = buf[k];
            float w = sw[s];
            acc.x += w * v.x; acc.y += w * v.y;
            acc.z += w * v.z; acc.w += w * v.w;
            int sp = s + PF;
            if (sp < B) buf[k] = F4[(size_t)sm[sp] * D4 + t4];
        }
    }
    while (c < NC) {
        O4[(size_t)c * D4 + t4] = acc;
        acc = make_float4(0.f, 0.f, 0.f, 0.f);
        ++c;
    }
}

// =====================================================================
extern "C" void kernel_launch(void* const* d_in, const int* in_sizes, int n_in,
                              void* d_out, int out_size) {
    const float* features;
    const int*   labels;
    if (in_sizes[0] == B) {
        labels   = (const int*)d_in[0];
        features = (const float*)d_in[1];
    } else {
        features = (const float*)d_in[0];
        labels   = (const int*)d_in[1];
    }
    float* out = (float*)d_out;

    (void)cudaFuncSetAttribute((const void*)k1_gram,
                               cudaFuncAttributeMaxDynamicSharedMemorySize,
                               SMEM_DYN);

    k0_prep<<<1, B>>>(labels);
    k1_gram<<<NCTA2, K1_THREADS, SMEM_DYN>>>(features);
    k2_weights<<<1, B>>>();
    k3_scatter<<<D4 / 256, 256>>>(features, out);
}

// round 12
// speedup vs baseline: 3.7999x; 1.0216x over previous
#include <cuda_runtime.h>
#include <cuda_bf16.h>
#include <math.h>
#include <stdint.h>

#define B      128
#define D      524288          // 512*32*32
#define D4     (D/4)           // 131072 float4 per row
#define NC     12
#define KT     128             // floats per row per chunk
#define NCHUNK (D/KT)          // 4096
#define NCTA2  296             // 2 CTAs per SM
#define K1_THREADS 512

// dynamic smem: two bf16 tiles [B][TP]
#define TP     136             // bf16 tile row pitch (128 + 8 pad)
#define TILE0  0
#define TILE1  (B * TP * 2)
#define SMEM_DYN (2 * B * TP * 2)   // 69632

// -------- device scratch --------
__device__ float g_pd[B * B];     // Gram (same-class entries used), slot-indexed
__device__ int   g_members[B];    // slot -> sample index
__device__ int   g_start[NC + 1];
__device__ int   g_cs[B];         // slot -> class start
__device__ int   g_ce[B];         // slot -> class end
__device__ int   g_band0[8];      // per 16-row strip: band start col (clamped)
__device__ int   g_ntile;         // 2 = banded (64-wide), 4 = wide fallback

// =====================================================================
// k0: zero pd; class-sort slots; per-strip clamped band bounds
// =====================================================================
__global__ void k0_prep(const int* __restrict__ labels) {
    __shared__ int sl[B];
    __shared__ int cstart[NC + 1];
    int t = threadIdx.x;
    sl[t] = labels[t];
    for (int p = t; p < B * B; p += B) g_pd[p] = 0.0f;
    __syncthreads();
    if (t == 0) {
        int cnt[NC];
        for (int c = 0; c < NC; ++c) cnt[c] = 0;
        for (int i = 0; i < B; ++i) cnt[sl[i]]++;
        int st = 0;
        for (int c = 0; c < NC; ++c) { cstart[c] = st; st += cnt[c]; }
        cstart[NC] = st;
    }
    __syncthreads();
    {
        int my = sl[t];
        int r = 0;
        for (int j = 0; j < t; ++j) r += (sl[j] == my);
        int slot = cstart[my] + r;
        g_members[slot] = t;
        g_cs[slot] = cstart[my];
        g_ce[slot] = cstart[my + 1];
    }
    if (t < NC + 1) g_start[t] = cstart[t];
    __syncthreads();
    if (t == 0) {
        int wide = 0;
        int b0[8];
        for (int s = 0; s < 8; ++s) {
            int nb0 = g_cs[16 * s] & ~7;
            if (nb0 > B - 64) nb0 = B - 64;        // band end <= 128
            b0[s] = nb0;
            if (g_ce[16 * s + 15] - nb0 > 64) wide = 1;
        }
        for (int s = 0; s < 8; ++s) g_band0[s] = wide ? 0 : b0[s];
        g_ntile = wide ? 4 : 2;
    }
}

// =====================================================================
// PTX helpers (base-ISA: ldmatrix, mma.sync)
// =====================================================================
__device__ __forceinline__ void ldsm4(uint32_t& r0, uint32_t& r1, uint32_t& r2,
                                      uint32_t& r3, uint32_t addr) {
    asm volatile("ldmatrix.sync.aligned.m8n8.x4.shared.b16 {%0,%1,%2,%3}, [%4];"
                 : "=r"(r0), "=r"(r1), "=r"(r2), "=r"(r3) : "r"(addr));
}
__device__ __forceinline__ void mma16816(float* c, uint32_t a0, uint32_t a1,
                                         uint32_t a2, uint32_t a3,
                                         uint32_t b0, uint32_t b1) {
    asm volatile(
        "mma.sync.aligned.m16n8k16.row.col.f32.bf16.bf16.f32 "
        "{%0,%1,%2,%3}, {%4,%5,%6,%7}, {%8,%9}, {%0,%1,%2,%3};"
        : "+f"(c[0]), "+f"(c[1]), "+f"(c[2]), "+f"(c[3])
        : "r"(a0), "r"(a1), "r"(a2), "r"(a3), "r"(b0), "r"(b1));
}

// =====================================================================
// k1: persistent banded bf16 mma.sync Gram, 2 CTAs/SM, software-
// pipelined: convert+STS current buf -> issue NEXT chunk's LDGs ->
// barrier -> HMMA (hides DRAM latency under tensor work).
// =====================================================================
__global__ void __launch_bounds__(K1_THREADS, 2)
k1_gram(const float* __restrict__ features) {
    extern __shared__ char smem[];
    __shared__ size_t s_roff[B];     // slot -> row base offset (float4 units)
    __shared__ int s_b0[8];
    __shared__ int s_nt;

    const int tid  = threadIdx.x;
    const int wid  = tid >> 5;
    const int lane = tid & 31;

    if (tid < B) s_roff[tid] = (size_t)g_members[tid] * D4;
    if (tid < 8) s_b0[tid] = g_band0[tid];
    if (tid == 0) s_nt = g_ntile;
    __syncthreads();

    const float4* F4 = (const float4*)features;
    const bool wide = (s_nt == 4);
    const int nseg  = wide ? 2 : 1;

    // ---- mma mapping: warp = (strip, band half) ----
    const int strip = wid >> 1;
    const int half  = wid & 1;
    const int m0    = strip * 16;
    const int wbase = s_b0[strip] + half * (wide ? 64 : 32);

    // ldmatrix lane address parts
    const int a_row    = m0 + (lane & 7) + ((lane >> 3) & 1) * 8;
    const int a_col8   = (lane >> 4) * 8;
    const int b_rowoff = (lane & 7) + ((lane >> 4) & 1) * 8;
    const int b_col8   = ((lane >> 3) & 1) * 8;

    // epilogue cell indices
    const int gid = lane >> 2;
    const int tig = lane & 3;
    const int r0 = m0 + gid, r1 = m0 + gid + 8;

    float acc[2][8];
    #pragma unroll
    for (int t = 0; t < 2; ++t)
        #pragma unroll
        for (int q = 0; q < 8; ++q) acc[t][q] = 0.0f;

    auto flush = [&](int base_n) {
        #pragma unroll
        for (int nt = 0; nt < 2; ++nt) {
            const int base = base_n + nt * 16;
            const int cA = base + tig * 2;
            const int cC = base + 8 + tig * 2;
            atomicAdd(&g_pd[r0 * B + cA],     acc[nt][0]);
            atomicAdd(&g_pd[r0 * B + cA + 1], acc[nt][1]);
            atomicAdd(&g_pd[r1 * B + cA],     acc[nt][2]);
            atomicAdd(&g_pd[r1 * B + cA + 1], acc[nt][3]);
            atomicAdd(&g_pd[r0 * B + cC],     acc[nt][4]);
            atomicAdd(&g_pd[r0 * B + cC + 1], acc[nt][5]);
            atomicAdd(&g_pd[r1 * B + cC],     acc[nt][6]);
            atomicAdd(&g_pd[r1 * B + cC + 1], acc[nt][7]);
        }
    };

    // ---- preload first chunk into registers (8 rows/warp, col=lane) ----
    float4 buf[8];
    {
        const size_t base4 = (size_t)blockIdx.x * (KT / 4) + lane;
        #pragma unroll
        for (int k = 0; k < 8; ++k)
            buf[k] = F4[s_roff[wid + k * 16] + base4];
    }

    int it = 0;
    for (int c = blockIdx.x; c < NCHUNK; c += NCTA2, ++it) {
        char* tilep = smem + ((it & 1) ? TILE1 : TILE0);
        const uint32_t tile_sh = (uint32_t)__cvta_generic_to_shared(tilep);

        // ---- convert current buf -> STS bf16 tile ----
        #pragma unroll
        for (int k = 0; k < 8; ++k) {
            const int row = wid + k * 16;
            __nv_bfloat162 h0 = __float22bfloat162_rn(make_float2(buf[k].x, buf[k].y));
            __nv_bfloat162 h1 = __float22bfloat162_rn(make_float2(buf[k].z, buf[k].w));
            uint2 v;
            v.x = *(uint32_t*)&h0;
            v.y = *(uint32_t*)&h1;
            *(uint2*)(tilep + row * (TP * 2) + lane * 8) = v;
        }

        // ---- issue NEXT chunk's LDGs (latency hidden under HMMA) ----
        {
            const int cn = c + NCTA2;
            if (cn < NCHUNK) {
                const size_t base4 = (size_t)cn * (KT / 4) + lane;
                #pragma unroll
                for (int k = 0; k < 8; ++k)
                    buf[k] = F4[s_roff[wid + k * 16] + base4];
            }
        }

        __syncthreads();   // tile[it&1] complete for all warps

        // ---- banded HMMA (1 segment) / wide fallback (2 segments) ----
        for (int seg = 0; seg < nseg; ++seg) {
            const int seg_base = wbase + seg * 32;
            #pragma unroll
            for (int ks = 0; ks < 8; ++ks) {
                const int k0c = ks * 16;
                uint32_t a0, a1, a2, a3;
                ldsm4(a0, a1, a2, a3,
                      tile_sh + (uint32_t)(a_row * TP + k0c + a_col8) * 2);
                #pragma unroll
                for (int nt = 0; nt < 2; ++nt) {
                    const int n0 = seg_base + nt * 16;
                    uint32_t b0, b1, b2, b3;
                    ldsm4(b0, b1, b2, b3,
                          tile_sh + (uint32_t)((n0 + b_rowoff) * TP + k0c + b_col8) * 2);
                    mma16816(&acc[nt][0], a0, a1, a2, a3, b0, b1);
                    mma16816(&acc[nt][4], a0, a1, a2, a3, b2, b3);
                }
            }
            if (wide) {        // pathological path: flush + rezero each chunk
                flush(seg_base);
                #pragma unroll
                for (int t = 0; t < 2; ++t)
                    #pragma unroll
                    for (int q = 0; q < 8; ++q) acc[t][q] = 0.0f;
            }
        }
    }

    if (!wide) flush(wbase);   // one atomic per cell per CTA
}

// =====================================================================
// k3: weights (folded from k2) + weighted class scatter-sum
// =====================================================================
#define PF 8
__global__ void __launch_bounds__(256) k3_scatter(const float* __restrict__ features,
                                                  float* __restrict__ out) {
    __shared__ float sw[B];
    __shared__ float sdiag[B];
    __shared__ float ssum;
    __shared__ int   sm[B];
    __shared__ int   sst[NC + 1];
    int t = threadIdx.x;
    if (t < B) {
        sm[t] = g_members[t];
        sdiag[t] = g_pd[t * B + t];
    }
    if (t < NC + 1) sst[t] = g_start[t];
    __syncthreads();

    // ---- per-block weight computation (was k2; L2-resident g_pd) ----
    if (t < B) {
        int st = g_cs[t], en = g_ce[t];
        float dsum = 0.0f;
        for (int b = st; b < en; ++b) {
            if (b == t) continue;
            float d2 = sdiag[t] + sdiag[b] - 2.0f * g_pd[t * B + b];
            dsum += (d2 > 0.0f) ? sqrtf(d2) : 0.0f;
        }
        sw[t] = 1.0f / (sqrtf(dsum * dsum + 25.0f) + 1e-12f);
    }
    __syncthreads();
    if (t == 0) {
        float S = 0.0f;
        for (int i = 0; i < B; ++i) S += sw[i];
        ssum = S + 1e-12f;
    }
    __syncthreads();
    if (t < B) sw[t] = sw[t] / ssum;
    __syncthreads();

    // ---- weighted scatter-sum, rolling slot pass, PF-deep prefetch ----
    const size_t t4 = (size_t)blockIdx.x * 256 + t;
    const float4* F4 = (const float4*)features;
    float4* O4 = (float4*)out;

    float4 buf[PF];
    #pragma unroll
    for (int k = 0; k < PF; ++k)
        buf[k] = F4[(size_t)sm[k] * D4 + t4];

    int c = 0;
    int nb = sst[1];
    float4 acc = make_float4(0.f, 0.f, 0.f, 0.f);

    for (int s0 = 0; s0 < B; s0 += PF) {
        #pragma unroll
        for (int k = 0; k < PF; ++k) {
            int s = s0 + k;
            while (s == nb && c < NC) {
                O4[(size_t)c * D4 + t4] = acc;
                acc = make_float4(0.f, 0.f, 0.f, 0.f);
                ++c;
                nb = sst[c + 1];
            }
            float4 v = buf[k];
            float w = sw[s];
            acc.x += w * v.x; acc.y += w * v.y;
            acc.z += w * v.z; acc.w += w * v.w;
            int sp = s + PF;
            if (sp < B) buf[k] = F4[(size_t)sm[sp] * D4 + t4];
        }
    }
    while (c < NC) {
        O4[(size_t)c * D4 + t4] = acc;
        acc = make_float4(0.f, 0.f, 0.f, 0.f);
        ++c;
    }
}

// =====================================================================
extern "C" void kernel_launch(void* const* d_in, const int* in_sizes, int n_in,
                              void* d_out, int out_size) {
    const float* features;
    const int*   labels;
    if (in_sizes[0] == B) {
        labels   = (const int*)d_in[0];
        features = (const float*)d_in[1];
    } else {
        features = (const float*)d_in[0];
        labels   = (const int*)d_in[1];
    }
    float* out = (float*)d_out;

    (void)cudaFuncSetAttribute((const void*)k1_gram,
                               cudaFuncAttributeMaxDynamicSharedMemorySize,
                               SMEM_DYN);

    k0_prep<<<1, B>>>(labels);
    k1_gram<<<NCTA2, K1_THREADS, SMEM_DYN>>>(features);
    k3_scatter<<<D4 / 256, 256>>>(features, out);
}

// round 13
// speedup vs baseline: 3.9293x; 1.0340x over previous
#include <cuda_runtime.h>
#include <cuda_bf16.h>
#include <math.h>
#include <stdint.h>

#define B      128
#define D      524288          // 512*32*32
#define D4     (D/4)           // 131072 float4 per row
#define NC     12
#define KT     128             // floats per row per chunk
#define NCHUNK (D/KT)          // 4096
#define NCTA2  296             // 2 CTAs per SM
#define K1_THREADS 512

// dynamic smem: two bf16 tiles [B][TP]
#define TP     136             // bf16 tile row pitch (128 + 8 pad)
#define TILE0  0
#define TILE1  (B * TP * 2)
#define SMEM_DYN (2 * B * TP * 2)   // 69632

// -------- device scratch --------
__device__ float g_pd[B * B];     // Gram (same-class entries used), slot-indexed
__device__ int   g_members[B];    // slot -> sample index
__device__ int   g_start[NC + 1];
__device__ int   g_cs[B];         // slot -> class start
__device__ int   g_ce[B];         // slot -> class end
__device__ int   g_band0[8];      // per 16-row strip: band start col (clamped)
__device__ int   g_ntile;         // 2 = banded (64-wide), 4 = wide fallback

// =====================================================================
// k0: zero pd; class-sort slots; band bounds. 1024 threads, vectorized.
// =====================================================================
__global__ void __launch_bounds__(1024) k0_prep(const int* __restrict__ labels) {
    __shared__ int sl[B];
    __shared__ int ccount[NC];
    __shared__ int cstart[NC + 1];
    int t = threadIdx.x;

    if (t < NC) ccount[t] = 0;
    if (t < B)  sl[t] = labels[t];
    // vectorized zero of g_pd: 4096 float4 / 1024 threads = 4 each
    {
        float4* P4 = (float4*)g_pd;
        #pragma unroll
        for (int k = 0; k < (B * B / 4) / 1024; ++k)
            P4[t + k * 1024] = make_float4(0.f, 0.f, 0.f, 0.f);
    }
    __syncthreads();

    if (t < B) atomicAdd(&ccount[sl[t]], 1);
    __syncthreads();
    if (t == 0) {
        int st = 0;
        for (int c = 0; c < NC; ++c) { cstart[c] = st; st += ccount[c]; }
        cstart[NC] = st;
    }
    __syncthreads();

    if (t < B) {
        int my = sl[t];
        int r = 0;
        for (int j = 0; j < t; ++j) r += (sl[j] == my);
        int slot = cstart[my] + r;
        g_members[slot] = t;
        g_cs[slot] = cstart[my];
        g_ce[slot] = cstart[my + 1];
    }
    if (t < NC + 1) g_start[t] = cstart[t];
    __syncthreads();

    if (t == 0) {
        int wide = 0;
        int b0[8];
        for (int s = 0; s < 8; ++s) {
            // class start of slot 16*s, via cstart of that slot's class
            int cls = 0;
            int slot = 16 * s;
            for (int c = 0; c < NC; ++c)
                if (slot >= cstart[c] && slot < cstart[c + 1]) cls = c;
            int nb0 = cstart[cls] & ~7;
            if (nb0 > B - 64) nb0 = B - 64;        // band end <= 128
            b0[s] = nb0;
            // class end of slot 16*s+15
            int slot2 = 16 * s + 15;
            int ce2 = B;
            for (int c = 0; c < NC; ++c)
                if (slot2 >= cstart[c] && slot2 < cstart[c + 1]) ce2 = cstart[c + 1];
            if (ce2 - nb0 > 64) wide = 1;
        }
        for (int s = 0; s < 8; ++s) g_band0[s] = wide ? 0 : b0[s];
        g_ntile = wide ? 4 : 2;
    }
}

// =====================================================================
// PTX helpers (base-ISA: ldmatrix, mma.sync)
// =====================================================================
__device__ __forceinline__ void ldsm4(uint32_t& r0, uint32_t& r1, uint32_t& r2,
                                      uint32_t& r3, uint32_t addr) {
    asm volatile("ldmatrix.sync.aligned.m8n8.x4.shared.b16 {%0,%1,%2,%3}, [%4];"
                 : "=r"(r0), "=r"(r1), "=r"(r2), "=r"(r3) : "r"(addr));
}
__device__ __forceinline__ void mma16816(float* c, uint32_t a0, uint32_t a1,
                                         uint32_t a2, uint32_t a3,
                                         uint32_t b0, uint32_t b1) {
    asm volatile(
        "mma.sync.aligned.m16n8k16.row.col.f32.bf16.bf16.f32 "
        "{%0,%1,%2,%3}, {%4,%5,%6,%7}, {%8,%9}, {%0,%1,%2,%3};"
        : "+f"(c[0]), "+f"(c[1]), "+f"(c[2]), "+f"(c[3])
        : "r"(a0), "r"(a1), "r"(a2), "r"(a3), "r"(b0), "r"(b1));
}

// =====================================================================
// k1: persistent banded bf16 mma.sync Gram, 2 CTAs/SM, software-
// pipelined: convert+STS current buf -> issue NEXT chunk's LDGs ->
// barrier -> HMMA (hides DRAM latency under tensor work).
// =====================================================================
__global__ void __launch_bounds__(K1_THREADS, 2)
k1_gram(const float* __restrict__ features) {
    extern __shared__ char smem[];
    __shared__ size_t s_roff[B];     // slot -> row base offset (float4 units)
    __shared__ int s_b0[8];
    __shared__ int s_nt;

    const int tid  = threadIdx.x;
    const int wid  = tid >> 5;
    const int lane = tid & 31;

    if (tid < B) s_roff[tid] = (size_t)g_members[tid] * D4;
    if (tid < 8) s_b0[tid] = g_band0[tid];
    if (tid == 0) s_nt = g_ntile;
    __syncthreads();

    const float4* F4 = (const float4*)features;
    const bool wide = (s_nt == 4);
    const int nseg  = wide ? 2 : 1;

    // ---- mma mapping: warp = (strip, band half) ----
    const int strip = wid >> 1;
    const int half  = wid & 1;
    const int m0    = strip * 16;
    const int wbase = s_b0[strip] + half * (wide ? 64 : 32);

    // ldmatrix lane address parts
    const int a_row    = m0 + (lane & 7) + ((lane >> 3) & 1) * 8;
    const int a_col8   = (lane >> 4) * 8;
    const int b_rowoff = (lane & 7) + ((lane >> 4) & 1) * 8;
    const int b_col8   = ((lane >> 3) & 1) * 8;

    // epilogue cell indices
    const int gid = lane >> 2;
    const int tig = lane & 3;
    const int r0 = m0 + gid, r1 = m0 + gid + 8;

    float acc[2][8];
    #pragma unroll
    for (int t = 0; t < 2; ++t)
        #pragma unroll
        for (int q = 0; q < 8; ++q) acc[t][q] = 0.0f;

    auto flush = [&](int base_n) {
        #pragma unroll
        for (int nt = 0; nt < 2; ++nt) {
            const int base = base_n + nt * 16;
            const int cA = base + tig * 2;
            const int cC = base + 8 + tig * 2;
            atomicAdd(&g_pd[r0 * B + cA],     acc[nt][0]);
            atomicAdd(&g_pd[r0 * B + cA + 1], acc[nt][1]);
            atomicAdd(&g_pd[r1 * B + cA],     acc[nt][2]);
            atomicAdd(&g_pd[r1 * B + cA + 1], acc[nt][3]);
            atomicAdd(&g_pd[r0 * B + cC],     acc[nt][4]);
            atomicAdd(&g_pd[r0 * B + cC + 1], acc[nt][5]);
            atomicAdd(&g_pd[r1 * B + cC],     acc[nt][6]);
            atomicAdd(&g_pd[r1 * B + cC + 1], acc[nt][7]);
        }
    };

    // ---- preload first chunk into registers (8 rows/warp, col=lane) ----
    float4 buf[8];
    {
        const size_t base4 = (size_t)blockIdx.x * (KT / 4) + lane;
        #pragma unroll
        for (int k = 0; k < 8; ++k)
            buf[k] = F4[s_roff[wid + k * 16] + base4];
    }

    int it = 0;
    for (int c = blockIdx.x; c < NCHUNK; c += NCTA2, ++it) {
        char* tilep = smem + ((it & 1) ? TILE1 : TILE0);
        const uint32_t tile_sh = (uint32_t)__cvta_generic_to_shared(tilep);

        // ---- convert current buf -> STS bf16 tile ----
        #pragma unroll
        for (int k = 0; k < 8; ++k) {
            const int row = wid + k * 16;
            __nv_bfloat162 h0 = __float22bfloat162_rn(make_float2(buf[k].x, buf[k].y));
            __nv_bfloat162 h1 = __float22bfloat162_rn(make_float2(buf[k].z, buf[k].w));
            uint2 v;
            v.x = *(uint32_t*)&h0;
            v.y = *(uint32_t*)&h1;
            *(uint2*)(tilep + row * (TP * 2) + lane * 8) = v;
        }

        // ---- issue NEXT chunk's LDGs (latency hidden under HMMA) ----
        {
            const int cn = c + NCTA2;
            if (cn < NCHUNK) {
                const size_t base4 = (size_t)cn * (KT / 4) + lane;
                #pragma unroll
                for (int k = 0; k < 8; ++k)
                    buf[k] = F4[s_roff[wid + k * 16] + base4];
            }
        }

        __syncthreads();   // tile[it&1] complete for all warps

        // ---- banded HMMA (1 segment) / wide fallback (2 segments) ----
        for (int seg = 0; seg < nseg; ++seg) {
            const int seg_base = wbase + seg * 32;
            #pragma unroll
            for (int ks = 0; ks < 8; ++ks) {
                const int k0c = ks * 16;
                uint32_t a0, a1, a2, a3;
                ldsm4(a0, a1, a2, a3,
                      tile_sh + (uint32_t)(a_row * TP + k0c + a_col8) * 2);
                #pragma unroll
                for (int nt = 0; nt < 2; ++nt) {
                    const int n0 = seg_base + nt * 16;
                    uint32_t b0, b1, b2, b3;
                    ldsm4(b0, b1, b2, b3,
                          tile_sh + (uint32_t)((n0 + b_rowoff) * TP + k0c + b_col8) * 2);
                    mma16816(&acc[nt][0], a0, a1, a2, a3, b0, b1);
                    mma16816(&acc[nt][4], a0, a1, a2, a3, b2, b3);
                }
            }
            if (wide) {        // pathological path: flush + rezero each chunk
                flush(seg_base);
                #pragma unroll
                for (int t = 0; t < 2; ++t)
                    #pragma unroll
                    for (int q = 0; q < 8; ++q) acc[t][q] = 0.0f;
            }
        }
    }

    if (!wide) flush(wbase);   // one atomic per cell per CTA
}

// =====================================================================
// k3: weights (folded) + weighted class scatter-sum
// =====================================================================
#define PF 8
__global__ void __launch_bounds__(256) k3_scatter(const float* __restrict__ features,
                                                  float* __restrict__ out) {
    __shared__ float sw[B];
    __shared__ float sdiag[B];
    __shared__ float ssum;
    __shared__ int   sm[B];
    __shared__ int   sst[NC + 1];
    int t = threadIdx.x;
    if (t < B) {
        sm[t] = g_members[t];
        sdiag[t] = g_pd[t * B + t];
    }
    if (t < NC + 1) sst[t] = g_start[t];
    __syncthreads();

    // ---- per-block weight computation (L2-resident g_pd) ----
    if (t < B) {
        int st = g_cs[t], en = g_ce[t];
        float dsum = 0.0f;
        for (int b = st; b < en; ++b) {
            if (b == t) continue;
            float d2 = sdiag[t] + sdiag[b] - 2.0f * g_pd[t * B + b];
            dsum += (d2 > 0.0f) ? sqrtf(d2) : 0.0f;
        }
        sw[t] = 1.0f / (sqrtf(dsum * dsum + 25.0f) + 1e-12f);
    }
    __syncthreads();
    if (t == 0) {
        float S = 0.0f;
        for (int i = 0; i < B; ++i) S += sw[i];
        ssum = S + 1e-12f;
    }
    __syncthreads();
    if (t < B) sw[t] = sw[t] / ssum;
    __syncthreads();

    // ---- weighted scatter-sum, rolling slot pass, PF-deep prefetch ----
    const size_t t4 = (size_t)blockIdx.x * 256 + t;
    const float4* F4 = (const float4*)features;
    float4* O4 = (float4*)out;

    float4 buf[PF];
    #pragma unroll
    for (int k = 0; k < PF; ++k)
        buf[k] = F4[(size_t)sm[k] * D4 + t4];

    int c = 0;
    int nb = sst[1];
    float4 acc = make_float4(0.f, 0.f, 0.f, 0.f);

    for (int s0 = 0; s0 < B; s0 += PF) {
        #pragma unroll
        for (int k = 0; k < PF; ++k) {
            int s = s0 + k;
            while (s == nb && c < NC) {
                O4[(size_t)c * D4 + t4] = acc;
                acc = make_float4(0.f, 0.f, 0.f, 0.f);
                ++c;
                nb = sst[c + 1];
            }
            float4 v = buf[k];
            float w = sw[s];
            acc.x += w * v.x; acc.y += w * v.y;
            acc.z += w * v.z; acc.w += w * v.w;
            int sp = s + PF;
            if (sp < B) buf[k] = F4[(size_t)sm[sp] * D4 + t4];
        }
    }
    while (c < NC) {
        O4[(size_t)c * D4 + t4] = acc;
        acc = make_float4(0.f, 0.f, 0.f, 0.f);
        ++c;
    }
}

// =====================================================================
extern "C" void kernel_launch(void* const* d_in, const int* in_sizes, int n_in,
                              void* d_out, int out_size) {
    const float* features;
    const int*   labels;
    if (in_sizes[0] == B) {
        labels   = (const int*)d_in[0];
        features = (const float*)d_in[1];
    } else {
        features = (const float*)d_in[0];
        labels   = (const int*)d_in[1];
    }
    float* out = (float*)d_out;

    (void)cudaFuncSetAttribute((const void*)k1_gram,
                               cudaFuncAttributeMaxDynamicSharedMemorySize,
                               SMEM_DYN);

    k0_prep<<<1, 1024>>>(labels);
    k1_gram<<<NCTA2, K1_THREADS, SMEM_DYN>>>(features);
    k3_scatter<<<D4 / 256, 256>>>(features, out);
}